// round 14
// baseline (speedup 1.0000x reference)
#include <cuda_runtime.h>
#include <cuda_fp16.h>
#include <cstdint>
#include <math.h>

// B=32, T=500, E=1024, D=1024, EMB=256, O=5000, olen=100, A=512
#define NBLK 296
#define NTHR 256

// ---------------- scratch layout (floats) ----------------
#define OFF_EYS   ((size_t)0)          // (100,32,256)
#define OFF_SB    ((size_t)819200)     // (100,32,2048)
#define OFF_SBX   ((size_t)7372800)    // (100,32,1024)
#define OFF_ENC   ((size_t)10649600)   // (32,500,512)
#define OFF_YW    ((size_t)18841600)   // (100,32,1024) eys@Wy precomputed
#define OFF_HSUM  ((size_t)22118400)   // (32,1024)
#define OFF_H     ((size_t)22151168)
#define OFF_H1    ((size_t)22183936)
#define OFF_YM    ((size_t)22216704)   // (100,32)
#define OFF_L512  ((size_t)22219904)   // (32,512)
#define OFF_MS    ((size_t)22236288)   // (32,8,2)
#define OFF_EXP   ((size_t)22236800)   // (32,5000)
#define OFF_CP    ((size_t)22396800)   // (32,9,1024) ctx partials
#define OFF_AST   ((size_t)22691712)   // (32,9,2) attn stats
#define OFF_PA    ((size_t)22692288)   // 1,179,648
#define OFF_PB    ((size_t)23871936)   // 1,179,648
#define OFF_HSH   ((size_t)25051584)   // hs in fp16: 16.384M halfs = 8.192M floats
#define SZ_TOTAL  ((size_t)33243584)

__device__ float g_scratch[SZ_TOTAL];
__device__ unsigned g_bar_cnt;
__device__ unsigned g_bar_cnt2;

// ---------------- grid barrier: REDG arrive + acquire poll ----------------
__device__ __forceinline__ void gsync(unsigned& gen) {
    gen += NBLK;
    __syncthreads();
    if (threadIdx.x == 0) {
        asm volatile("red.release.gpu.global.add.u32 [%0], 1;"
                     :: "l"(&g_bar_cnt) : "memory");
        unsigned v;
        while (true) {
            asm volatile("ld.acquire.gpu.global.u32 %0, [%1];"
                         : "=r"(v) : "l"(&g_bar_cnt) : "memory");
            if ((int)(v - gen) >= 0) break;
        }
    }
    __syncthreads();
}

__device__ __forceinline__ float sigm(float x) { return 1.f / (1.f + expf(-x)); }

// ---------------- GEMM building blocks (32 rows x 128 cols tile) ----------------
__device__ __forceinline__ void load_A(const float* A, int ldA, int k0, float* sAT) {
    int tid = threadIdx.x;
    int r = tid & 31, q = tid >> 5;
    float4 v = *(const float4*)(A + (size_t)r * ldA + k0 + q * 4);
    sAT[(q*4+0)*32 + r] = v.x; sAT[(q*4+1)*32 + r] = v.y;
    sAT[(q*4+2)*32 + r] = v.z; sAT[(q*4+3)*32 + r] = v.w;
}

__device__ __forceinline__ void load_W_async(const float* W, int ldW, int k0,
                                             int colBase, int ncols, float* sWdst) {
    unsigned sbase = (unsigned)__cvta_generic_to_shared(sWdst);
    int tid = threadIdx.x;
    #pragma unroll
    for (int v4 = 0; v4 < 4; v4++) {
        int id = tid + v4 * 256;
        int kr = id >> 5;
        int c4 = (id & 31) << 2;
        int rem = ncols - c4;
        int sz = rem >= 4 ? 16 : (rem > 0 ? rem * 4 : 0);
        int cc = (sz > 0) ? c4 : 0;
        const float* src = W + (size_t)(k0 + kr) * ldW + colBase + cc;
        unsigned d = sbase + (unsigned)((kr * 128 + c4) * 4);
        asm volatile("cp.async.cg.shared.global [%0], [%1], 16, %2;"
                     :: "r"(d), "l"(src), "r"(sz));
    }
}

// prefetch first W tile of an upcoming GEMM phase (issued during prior phase)
__device__ __forceinline__ void prefetchW(const float* W, int ldW, int k0,
                                          int colBase, int ncols, float* wbuf) {
    __syncthreads();   // ensure prior phase readers of wbuf are done
    load_W_async(W, ldW, k0, colBase, ncols, wbuf);
    asm volatile("cp.async.commit_group;" ::: "memory");
}

// packed f32x2 MMA, 8 rows x 2 cols per thread
__device__ __forceinline__ void mma_chunk(unsigned long long acc[4][2],
                                          const float* sAT, const float* sW) {
    int tid = threadIdx.x;
    int ct = tid & 63, rt = tid >> 6;
    #pragma unroll
    for (int kk = 0; kk < 32; kk++) {
        const unsigned long long* ap =
            (const unsigned long long*)(sAT + kk * 32 + rt * 8);
        unsigned long long a0 = ap[0], a1 = ap[1], a2 = ap[2], a3 = ap[3];
        float2 w = *(const float2*)(sW + kk * 128 + ct * 2);
        unsigned long long w0, w1;
        asm("mov.b64 %0, {%1,%1};" : "=l"(w0) : "f"(w.x));
        asm("mov.b64 %0, {%1,%1};" : "=l"(w1) : "f"(w.y));
        #define F2X(ac, av, wv) \
            asm("fma.rn.f32x2 %0, %1, %2, %0;" : "+l"(ac) : "l"(av), "l"(wv));
        F2X(acc[0][0], a0, w0) F2X(acc[0][1], a0, w1)
        F2X(acc[1][0], a1, w0) F2X(acc[1][1], a1, w1)
        F2X(acc[2][0], a2, w0) F2X(acc[2][1], a2, w1)
        F2X(acc[3][0], a3, w0) F2X(acc[3][1], a3, w1)
        #undef F2X
    }
}

__device__ __forceinline__ void store_tile(unsigned long long acc[4][2],
                                           float* outBase, int Ntot, int ncols) {
    int tid = threadIdx.x;
    int ct = tid & 63, rt = tid >> 6;
    int c = ct * 2;
    if (c + 2 > ncols) return;
    #pragma unroll
    for (int i = 0; i < 4; i++) {
        float lo0, hi0, lo1, hi1;
        asm("mov.b64 {%0,%1}, %2;" : "=f"(lo0), "=f"(hi0) : "l"(acc[i][0]));
        asm("mov.b64 {%0,%1}, %2;" : "=f"(lo1), "=f"(hi1) : "l"(acc[i][1]));
        float* d0 = outBase + (size_t)(rt * 8 + 2 * i) * Ntot + c;
        float* d1 = outBase + (size_t)(rt * 8 + 2 * i + 1) * Ntot + c;
        *(float2*)d0 = make_float2(lo0, lo1);
        *(float2*)d1 = make_float2(hi0, hi1);
    }
}

struct GPair { const float* A; int ldA; const float* W; int ldW; int K; };

__device__ void gemm_tile(const GPair* pr, int np, int ks, int KS,
                          int colBase, int ncols, float* outSlot, int Ntot,
                          float* abuf, float* wbuf, int wpre) {
    unsigned long long acc[4][2] = {};
    int pidx[8], koff[8];
    int m = 0, gc = 0;
    for (int p = 0; p < np; p++)
        for (int k0 = 0; k0 < pr[p].K; k0 += 32)
            if ((gc++ % KS) == ks) { pidx[m] = p; koff[m] = k0; m++; }

    __syncthreads();
    if (m > 0) {
        if (!wpre) {
            load_W_async(pr[pidx[0]].W, pr[pidx[0]].ldW, koff[0], colBase, ncols, wbuf);
            asm volatile("cp.async.commit_group;" ::: "memory");
        }
        load_A(pr[pidx[0]].A, pr[pidx[0]].ldA, koff[0], abuf);
    }
    for (int i = 0; i < m; i++) {
        asm volatile("cp.async.wait_group 0;" ::: "memory");
        __syncthreads();
        if (i + 1 < m) {
            load_W_async(pr[pidx[i+1]].W, pr[pidx[i+1]].ldW, koff[i+1],
                         colBase, ncols, wbuf + ((i + 1) & 1) * 4096);
            asm volatile("cp.async.commit_group;" ::: "memory");
            load_A(pr[pidx[i+1]].A, pr[pidx[i+1]].ldA, koff[i+1],
                   abuf + ((i + 1) & 1) * 1024);
        }
        mma_chunk(acc, abuf + (i & 1) * 1024, wbuf + (i & 1) * 4096);
    }
    store_tile(acc, outSlot, Ntot, ncols);
}

// GEMM tile with A = combined context vector (cvec built inline from cp/ast)
__device__ void gemm_tile_cf(const float* W, int ldW, int ks, int KS,
                             int colBase, float* outSlot, int Ntot,
                             const float* cp, const float* ast,
                             float* abuf, float* wbuf, int wpre) {
    unsigned long long acc[4][2] = {};
    int koff[8];
    int m = 0;
    for (int k0 = 0; k0 < 1024; k0 += 32)
        if (((k0 >> 5) % KS) == ks) koff[m++] = k0;

    int tid = threadIdx.x;
    int r = tid & 31, q = tid >> 5;
    // per-thread combine coefficients for batch row r
    float M = -1e30f;
    #pragma unroll
    for (int ch = 0; ch < 9; ch++) M = fmaxf(M, ast[(r * 9 + ch) * 2]);
    float Z = 0.f;
    float scl[9];
    #pragma unroll
    for (int ch = 0; ch < 9; ch++) {
        scl[ch] = expf(ast[(r * 9 + ch) * 2] - M);
        Z += ast[(r * 9 + ch) * 2 + 1] * scl[ch];
    }
    float inv = 1.f / Z;
    #pragma unroll
    for (int ch = 0; ch < 9; ch++) scl[ch] *= inv;

    __syncthreads();
    if (!wpre) {
        load_W_async(W, ldW, koff[0], colBase, 128, wbuf);
        asm volatile("cp.async.commit_group;" ::: "memory");
    }
    // build A chunk 0
    {
        float4 s = {0, 0, 0, 0};
        #pragma unroll
        for (int ch = 0; ch < 9; ch++) {
            float4 v = *(const float4*)(cp + (size_t)(r * 9 + ch) * 1024 + koff[0] + q * 4);
            s.x = fmaf(v.x, scl[ch], s.x);
            s.y = fmaf(v.y, scl[ch], s.y);
            s.z = fmaf(v.z, scl[ch], s.z);
            s.w = fmaf(v.w, scl[ch], s.w);
        }
        abuf[(q*4+0)*32 + r] = s.x; abuf[(q*4+1)*32 + r] = s.y;
        abuf[(q*4+2)*32 + r] = s.z; abuf[(q*4+3)*32 + r] = s.w;
    }
    for (int i = 0; i < m; i++) {
        asm volatile("cp.async.wait_group 0;" ::: "memory");
        __syncthreads();
        if (i + 1 < m) {
            load_W_async(W, ldW, koff[i+1], colBase, 128, wbuf + ((i + 1) & 1) * 4096);
            asm volatile("cp.async.commit_group;" ::: "memory");
            float* ab = abuf + ((i + 1) & 1) * 1024;
            float4 s = {0, 0, 0, 0};
            #pragma unroll
            for (int ch = 0; ch < 9; ch++) {
                float4 v = *(const float4*)(cp + (size_t)(r * 9 + ch) * 1024 + koff[i+1] + q * 4);
                s.x = fmaf(v.x, scl[ch], s.x);
                s.y = fmaf(v.y, scl[ch], s.y);
                s.z = fmaf(v.z, scl[ch], s.z);
                s.w = fmaf(v.w, scl[ch], s.w);
            }
            ab[(q*4+0)*32 + r] = s.x; ab[(q*4+1)*32 + r] = s.y;
            ab[(q*4+2)*32 + r] = s.z; ab[(q*4+3)*32 + r] = s.w;
        }
        mma_chunk(acc, abuf + (i & 1) * 1024, wbuf + (i & 1) * 4096);
    }
    store_tile(acc, outSlot, Ntot, 128);
}

// ---------------- 64x64 tiled SGEMM (precompute) ----------
__device__ void tiled64(const float* __restrict__ A, const float* __restrict__ W,
                        const float* __restrict__ bias, float* __restrict__ C,
                        int N, int K, int act, int cx, int cy, float* USM) {
    float* sAT = USM;          // [16][68]
    float* sW  = USM + 1088;   // [16][64]
    int rowBase = cy << 6;
    int colBase = cx << 6;
    int tx = threadIdx.x & 15;
    int ty = threadIdx.x >> 4;
    float acc[4][4];
    #pragma unroll
    for (int i = 0; i < 4; i++)
        #pragma unroll
        for (int j = 0; j < 4; j++) acc[i][j] = 0.f;

    for (int k0 = 0; k0 < K; k0 += 16) {
        __syncthreads();
        {
            int r = threadIdx.x >> 2;
            int c4 = (threadIdx.x & 3) << 2;
            float4 v = *(const float4*)(A + (size_t)(rowBase + r) * K + k0 + c4);
            sAT[(c4+0)*68 + r] = v.x; sAT[(c4+1)*68 + r] = v.y;
            sAT[(c4+2)*68 + r] = v.z; sAT[(c4+3)*68 + r] = v.w;
            int kr = threadIdx.x >> 4;
            int wc = (threadIdx.x & 15) << 2;
            *(float4*)&sW[kr*64 + wc] = *(const float4*)(W + (size_t)(k0 + kr) * N + colBase + wc);
        }
        __syncthreads();
        #pragma unroll
        for (int kk = 0; kk < 16; kk++) {
            float4 a4 = *(const float4*)&sAT[kk*68 + (ty << 2)];
            float4 w4 = *(const float4*)&sW[kk*64 + (tx << 2)];
            float av[4] = {a4.x, a4.y, a4.z, a4.w};
            float wv[4] = {w4.x, w4.y, w4.z, w4.w};
            #pragma unroll
            for (int i = 0; i < 4; i++)
                #pragma unroll
                for (int j = 0; j < 4; j++)
                    acc[i][j] = fmaf(av[i], wv[j], acc[i][j]);
        }
    }
    #pragma unroll
    for (int i = 0; i < 4; i++) {
        int r = rowBase + (ty << 2) + i;
        #pragma unroll
        for (int j = 0; j < 4; j++) {
            int c = colBase + (tx << 2) + j;
            float v = acc[i][j];
            if (bias) v += bias[c];
            if (act == 1) v = tanhf(v);
            C[(size_t)r * N + c] = v;
        }
    }
}

// ---------------- megakernel ----------------
struct MKArgs {
    const float *hs, *embed, *W1_W, *b1_W, *W1_Wx, *b1_Wx, *Wenc;
    const float *U1, *Ux1, *U2, *b2, *Wc, *Ux2, *bUx2, *Wcx;
    const float *Ws, *bs, *Wy, *We, *Wlogit, *blogit, *Wdec, *Winit, *binit;
    const int *hlens, *ys;
    float* out;
};

__global__ void __launch_bounds__(NTHR, 2) k_mega(MKArgs a) {
    extern __shared__ float SM[];
    float* abuf = SM;          // 2048 floats
    float* wbuf = SM + 2048;   // 8192 floats

    float* eys  = g_scratch + OFF_EYS;
    float* sb   = g_scratch + OFF_SB;
    float* sbx  = g_scratch + OFF_SBX;
    float* enc  = g_scratch + OFF_ENC;
    float* yw   = g_scratch + OFF_YW;
    float* hsum = g_scratch + OFF_HSUM;
    float* h    = g_scratch + OFF_H;
    float* h1   = g_scratch + OFF_H1;
    float* ym   = g_scratch + OFF_YM;
    float* l512 = g_scratch + OFF_L512;
    float* ms   = g_scratch + OFF_MS;
    float* expb = g_scratch + OFF_EXP;
    float* cp   = g_scratch + OFF_CP;
    float* ast  = g_scratch + OFF_AST;
    float* pA   = g_scratch + OFF_PA;
    float* pB   = g_scratch + OFF_PB;
    __half* hsH = (__half*)(g_scratch + OFF_HSH);

    const int tid = threadIdx.x;
    const int bid = blockIdx.x;
    unsigned gen = 0;

    // ===== phase 0a: setup (ymask, eys gather, hsum, hs->fp16) =====
    if (bid == 0 && tid < 32) {
        int b = tid;
        int yl = 0;
        for (int j = 0; j < 99; j++) yl += (a.ys[b * 99 + j] != -1) ? 1 : 0;
        for (int i = 0; i < 100; i++)
            ym[i * 32 + b] = (i < yl + 1) ? 1.f : 0.f;
    }
    for (int idx4 = bid * NTHR + tid; idx4 < 204800; idx4 += NBLK * NTHR) {
        int row = idx4 >> 6;
        int i = row >> 5, b = row & 31;
        int tok = 4999;
        if (i > 0) { int v = a.ys[b * 99 + i - 1]; tok = (v < 0) ? 4999 : v; }
        int c4 = (idx4 & 63) << 2;
        *(float4*)&eys[(size_t)row * 256 + c4] =
            *(const float4*)&a.embed[(size_t)tok * 256 + c4];
    }
    // hs -> fp16 (16.384M elements, 4 per iter)
    for (int i4 = bid * NTHR + tid; i4 < 4096000; i4 += NBLK * NTHR) {
        float4 v = *((const float4*)a.hs + i4);
        __half2 p0 = __floats2half2_rn(v.x, v.y);
        __half2 p1 = __floats2half2_rn(v.z, v.w);
        ((__half2*)hsH)[(size_t)i4 * 2]     = p0;
        ((__half2*)hsH)[(size_t)i4 * 2 + 1] = p1;
    }
    for (int t = bid; t < 256; t += NBLK) {
        int b = t >> 3, ech = t & 7;
        if (tid < 128) {
            int e = ech * 128 + tid;
            const float* base = a.hs + (size_t)b * 512000 + e;
            float s0 = 0.f, s1 = 0.f;
            for (int tt = 0; tt < 500; tt += 2) {
                s0 += base[(size_t)tt * 1024];
                s1 += base[(size_t)(tt + 1) * 1024];
            }
            hsum[b * 1024 + e] = (s0 + s1) / (float)a.hlens[b];
        }
    }
    gsync(gen);

    // ===== phase 0b: sb, sbx, yW, enc via 64x64 tiles (5200 tiles) =====
    for (int t = bid; t < 5200; t += NBLK) {
        if (t < 1600)       tiled64(eys, a.W1_W, a.b1_W, sb, 2048, 256, 0,
                                    t % 32, t / 32, SM);
        else if (t < 2400)  tiled64(eys, a.W1_Wx, a.b1_Wx, sbx, 1024, 256, 0,
                                    (t - 1600) % 16, (t - 1600) / 16, SM);
        else if (t < 3200)  tiled64(eys, a.Wy, nullptr, yw, 1024, 256, 0,
                                    (t - 2400) % 16, (t - 2400) / 16, SM);
        else                tiled64(a.hs, a.Wenc, nullptr, enc, 512, 1024, 1,
                                    (t - 3200) % 8, (t - 3200) / 8, SM);
    }
    gsync(gen);

    // ===== h0 = hsum @ Winit + binit : 128 tiles =====
    for (int t = bid; t < 128; t += NBLK) {
        int ct = t & 7, ks = t >> 3;
        GPair p = {hsum, 1024, a.Winit, 1024, 1024};
        gemm_tile(&p, 1, ks, 16, ct * 128, 128,
                  pA + (size_t)ks * 32768 + ct * 128, 1024, abuf, wbuf, 0);
    }
    gsync(gen);
    for (int idx = bid * NTHR + tid; idx < 32768; idx += NBLK * NTHR) {
        float s = a.binit[idx & 1023];
        #pragma unroll 4
        for (int sI = 0; sI < 16; sI++) s += pA[(size_t)sI * 32768 + idx];
        h[idx] = s;
    }
    // prefetch first P1 W tile (step 0)
    if (bid < 288) {
        int ct = bid % 24, ks = bid / 24;
        if (ct < 16) prefetchW(a.U1, 2048, ks * 32, ct * 128, 128, wbuf);
        else         prefetchW(a.Ux1, 1024, ks * 32, (ct - 16) * 128, 128, wbuf);
    }
    gsync(gen);

    for (int step = 0; step < 100; step++) {
        // ===== P1: fused 9b(step-1) + gate1 = [h@U1 | h@Ux1], 288 tiles =====
        if (step > 0) {
            for (int t = bid; t < 256; t += NBLK) {
                int b = t & 31, q = t >> 5;
                float gm = -1e30f;
                #pragma unroll
                for (int w = 0; w < 8; w++) gm = fmaxf(gm, ms[(b * 8 + w) * 2]);
                float gs = 0.f;
                #pragma unroll
                for (int w = 0; w < 8; w++)
                    gs += ms[(b * 8 + w) * 2 + 1] * expf(ms[(b * 8 + w) * 2] - gm);
                float scale = expf(ms[(b * 8 + q) * 2] - gm) / gs;
                float* o = a.out + (size_t)b * 500000 + (size_t)(step - 1) * 5000 + q * 625;
                const float* src = expb + (size_t)b * 5000 + q * 625;
                for (int j0 = tid; j0 < 625; j0 += NTHR) __stcs(o + j0, src[j0] * scale);
            }
        }
        for (int t = bid; t < 288; t += NBLK) {
            int ct = t % 24, ks = t / 24;      // KS=12
            if (ct < 16) {
                GPair p = {h, 1024, a.U1, 2048, 1024};
                gemm_tile(&p, 1, ks, 12, ct * 128, 128,
                          pA + (size_t)ks * 98304 + ct * 128, 3072, abuf, wbuf, 1);
            } else {
                GPair p = {h, 1024, a.Ux1, 1024, 1024};
                gemm_tile(&p, 1, ks, 12, (ct - 16) * 128, 128,
                          pA + (size_t)ks * 98304 + 2048 + (ct - 16) * 128, 3072,
                          abuf, wbuf, 1);
            }
        }
        gsync(gen);

        // ===== P2: ew1 (float4, 12-slot reduce) -> h1 =====
        for (int q = bid * NTHR + tid; q < 8192; q += NBLK * NTHR) {
            int r = q >> 8, j4 = (q & 255) << 2;
            float4 pr = {0,0,0,0}, uv = {0,0,0,0}, hx = {0,0,0,0};
            #pragma unroll
            for (int s = 0; s < 12; s++) {
                const float* P = pA + (size_t)s * 98304 + (size_t)r * 3072;
                float4 v;
                v = *(const float4*)(P + j4);        pr.x+=v.x; pr.y+=v.y; pr.z+=v.z; pr.w+=v.w;
                v = *(const float4*)(P + 1024 + j4); uv.x+=v.x; uv.y+=v.y; uv.z+=v.z; uv.w+=v.w;
                v = *(const float4*)(P + 2048 + j4); hx.x+=v.x; hx.y+=v.y; hx.z+=v.z; hx.w+=v.w;
            }
            const float* x_ = sb + (size_t)step * 65536 + (size_t)r * 2048;
            float4 xa = *(const float4*)(x_ + j4);
            float4 xb = *(const float4*)(x_ + 1024 + j4);
            float4 xc = *(const float4*)(sbx + (size_t)step * 32768 + r * 1024 + j4);
            float4 ho = *(const float4*)(h + r * 1024 + j4);
            float m = ym[step * 32 + r];
            float4 res;
            #define EW1(L) { \
                float p_ = sigm(pr.L + xa.L); \
                float u_ = sigm(uv.L + xb.L); \
                float t_ = tanhf(hx.L * p_ + xc.L); \
                res.L = m * (u_ * ho.L + (1.f - u_) * t_) + (1.f - m) * ho.L; }
            EW1(x) EW1(y) EW1(z) EW1(w)
            #undef EW1
            *(float4*)(h1 + r * 1024 + j4) = res;
        }
        // prefetch first P3 W tile
        if (bid < 280) {
            int t = bid;
            if (t < 40)       prefetchW(a.Wdec, 512, (t >> 2) * 32, (t & 3) * 128, 128, wbuf);
            else if (t < 200) { int tt = t - 40;
                                prefetchW(a.U2, 2048, (tt / 16) * 32, (tt % 16) * 128, 128, wbuf); }
            else              { int tt = t - 200;
                                prefetchW(a.Ux2, 1024, (tt >> 3) * 32, (tt & 7) * 128, 128, wbuf); }
        }
        gsync(gen);

        // ===== P3: dq + h1@U2 + h1@Ux2 partials, 280 tiles (KS=10) =====
        for (int t = bid; t < 280; t += NBLK) {
            if (t < 40) {
                int ct = t & 3, ks = t >> 2;
                GPair p = {h1, 1024, a.Wdec, 512, 1024};
                gemm_tile(&p, 1, ks, 10, ct * 128, 128,
                          pB + (size_t)ks * 16384 + ct * 128, 512, abuf, wbuf, 1);
            } else if (t < 200) {
                int tt = t - 40, ct = tt % 16, ks = tt / 16;
                GPair p = {h1, 1024, a.U2, 2048, 1024};
                gemm_tile(&p, 1, ks, 10, ct * 128, 128,
                          pA + (size_t)ks * 98304 + ct * 128, 3072, abuf, wbuf, 1);
            } else {
                int tt = t - 200, ct = tt & 7, ks = tt >> 3;
                GPair p = {h1, 1024, a.Ux2, 1024, 1024};
                gemm_tile(&p, 1, ks, 10, ct * 128, 128,
                          pA + (size_t)ks * 98304 + 2048 + ct * 128, 3072, abuf, wbuf, 1);
            }
        }
        gsync(gen);

        // ===== P4: online-softmax attention, 288 tiles (b x 9 t-chunks of 56) =====
        for (int t = bid; t < 288; t += NBLK) {
            int b = t & 31, tch = t >> 5;
            __syncthreads();
            float* dqs = SM;           // 512
            float* sc  = SM + 512;     // 56
            for (int j = tid; j < 512; j += NTHR) {
                float s = 0.f;
                #pragma unroll
                for (int sI = 0; sI < 10; sI++)
                    s += pB[(size_t)sI * 16384 + b * 512 + j];
                dqs[j] = tanhf(s);
            }
            __syncthreads();
            int t0 = tch * 56;
            int tn = 500 - t0; if (tn > 56) tn = 56;
            int w = tid >> 5, l = tid & 31;
            int hl = a.hlens[b];
            for (int tt = w; tt < tn; tt += 8) {
                const float* row = enc + ((size_t)b * 500 + t0 + tt) * 512;
                float s = 0.f;
                #pragma unroll
                for (int qq = 0; qq < 16; qq++)
                    s = fmaf(row[l + qq * 32], dqs[l + qq * 32], s);
                #pragma unroll
                for (int o = 16; o; o >>= 1) s += __shfl_xor_sync(0xffffffffu, s, o);
                if (l == 0) sc[tt] = (t0 + tt < hl) ? s : -1e9f;
            }
            __syncthreads();
            if (tid < 32) {
                float mloc = -1e30f;
                for (int i = l; i < tn; i += 32) mloc = fmaxf(mloc, sc[i]);
                #pragma unroll
                for (int o = 16; o; o >>= 1) mloc = fmaxf(mloc, __shfl_xor_sync(0xffffffffu, mloc, o));
                float ssum = 0.f;
                for (int i = l; i < tn; i += 32) {
                    float e = expf(sc[i] - mloc);
                    sc[i] = e;
                    ssum += e;
                }
                #pragma unroll
                for (int o = 16; o; o >>= 1) ssum += __shfl_xor_sync(0xffffffffu, ssum, o);
                if (l == 0) {
                    ast[(b * 9 + tch) * 2]     = mloc;
                    ast[(b * 9 + tch) * 2 + 1] = ssum;
                }
            }
            __syncthreads();
            // ctx partial: 256 threads x 4 e-cols, fp16 hs streamed
            int e0 = tid * 4;
            float4 acc = {0,0,0,0};
            const __half* hb = hsH + (size_t)b * 512000 + (size_t)t0 * 1024 + e0;
            #pragma unroll 4
            for (int tt = 0; tt < tn; tt++) {
                float wg = sc[tt];
                float2 raw = __ldcs((const float2*)(hb + (size_t)tt * 1024));
                __half2 h01 = ((__half2*)&raw)[0];
                __half2 h23 = ((__half2*)&raw)[1];
                float2 f01 = __half22float2(h01);
                float2 f23 = __half22float2(h23);
                acc.x = fmaf(wg, f01.x, acc.x);
                acc.y = fmaf(wg, f01.y, acc.y);
                acc.z = fmaf(wg, f23.x, acc.z);
                acc.w = fmaf(wg, f23.y, acc.w);
            }
            *(float4*)(cp + (size_t)(b * 9 + tch) * 1024 + e0) = acc;
            __syncthreads();
        }
        // prefetch first P6 W tile
        if (bid < 288) {
            int t = bid;
            if (t < 144)      prefetchW(a.Wc, 2048, (t / 16) * 32, (t % 16) * 128, 128, wbuf);
            else if (t < 216) { int tt = t - 144;
                                prefetchW(a.Wcx, 1024, (tt >> 3) * 32, (tt & 7) * 128, 128, wbuf); }
            else              { int tt = t - 216;
                                prefetchW(a.We, 1024, (tt >> 3) * 32, (tt & 7) * 128, 128, wbuf); }
        }
        gsync(gen);

        // ===== P6: c@Wc | c@Wcx | c@We with inline ctx combine, 288 tiles (KS=9) =====
        for (int t = bid; t < 288; t += NBLK) {
            if (t < 144) {
                int ct = t % 16, ks = t / 16;
                gemm_tile_cf(a.Wc, 2048, ks, 9, ct * 128,
                             pB + (size_t)ks * 131072 + ct * 128, 4096,
                             cp, ast, abuf, wbuf, 1);
            } else if (t < 216) {
                int tt = t - 144, ct = tt & 7, ks = tt >> 3;
                gemm_tile_cf(a.Wcx, 1024, ks, 9, ct * 128,
                             pB + (size_t)ks * 131072 + 2048 + ct * 128, 4096,
                             cp, ast, abuf, wbuf, 1);
            } else {
                int tt = t - 216, ct = tt & 7, ks = tt >> 3;
                gemm_tile_cf(a.We, 1024, ks, 9, ct * 128,
                             pB + (size_t)ks * 131072 + 3072 + ct * 128, 4096,
                             cp, ast, abuf, wbuf, 1);
            }
        }
        gsync(gen);

        // ===== P7: ew2 (float4) -> h (=h2) =====
        for (int q = bid * NTHR + tid; q < 8192; q += NBLK * NTHR) {
            int r = q >> 8, j4 = (q & 255) << 2;
            float4 pr = {0,0,0,0}, uv = {0,0,0,0}, hx = {0,0,0,0}, cx = {0,0,0,0};
            #pragma unroll
            for (int s = 0; s < 10; s++) {
                const float* P = pA + (size_t)s * 98304 + (size_t)r * 3072;
                float4 v;
                v = *(const float4*)(P + j4);        pr.x+=v.x; pr.y+=v.y; pr.z+=v.z; pr.w+=v.w;
                v = *(const float4*)(P + 1024 + j4); uv.x+=v.x; uv.y+=v.y; uv.z+=v.z; uv.w+=v.w;
                v = *(const float4*)(P + 2048 + j4); hx.x+=v.x; hx.y+=v.y; hx.z+=v.z; hx.w+=v.w;
            }
            #pragma unroll
            for (int s = 0; s < 9; s++) {
                const float* P = pB + (size_t)s * 131072 + (size_t)r * 4096;
                float4 v;
                v = *(const float4*)(P + j4);        pr.x+=v.x; pr.y+=v.y; pr.z+=v.z; pr.w+=v.w;
                v = *(const float4*)(P + 1024 + j4); uv.x+=v.x; uv.y+=v.y; uv.z+=v.z; uv.w+=v.w;
                v = *(const float4*)(P + 2048 + j4); cx.x+=v.x; cx.y+=v.y; cx.z+=v.z; cx.w+=v.w;
            }
            float4 ba = *(const float4*)(a.b2 + j4);
            float4 bb = *(const float4*)(a.b2 + 1024 + j4);
            float4 bu = *(const float4*)(a.bUx2 + j4);
            float4 h1v = *(const float4*)(h1 + r * 1024 + j4);
            float m = ym[step * 32 + r];
            float4 res;
            #define EW2(L) { \
                float p_ = sigm(pr.L + ba.L); \
                float u_ = sigm(uv.L + bb.L); \
                float t_ = tanhf((hx.L + bu.L) * p_ + cx.L); \
                res.L = m * (u_ * h1v.L + (1.f - u_) * t_) + (1.f - m) * h1v.L; }
            EW2(x) EW2(y) EW2(z) EW2(w)
            #undef EW2
            *(float4*)(h + r * 1024 + j4) = res;
        }
        // prefetch P8 W tile (m=1 phase)
        if (bid < 256)
            prefetchW(a.Ws, 1024, (bid >> 3) * 32, (bid & 7) * 128, 128, wbuf);
        gsync(gen);

        // ===== P8: h2@Ws, 256 tiles (KS=32, m=1, W prefetched) =====
        for (int t = bid; t < 256; t += NBLK) {
            int ct = t & 7, ks = t >> 3;
            GPair p = {h, 1024, a.Ws, 1024, 1024};
            gemm_tile(&p, 1, ks, 32, ct * 128, 128,
                      pA + (size_t)ks * 32768 + ct * 128, 1024, abuf, wbuf, 1);
        }
        gsync(gen);

        // ===== P9: pool (32 Ws slots + 9 We slots + yW + bs, pairmax) -> l512 =====
        for (int idx = bid * NTHR + tid; idx < 16384; idx += NBLK * NTHR) {
            int r = idx >> 9, p2 = idx & 511;
            float2 v = *(const float2*)(a.bs + 2 * p2);
            float2 yv = *(const float2*)(yw + (size_t)step * 32768 + r * 1024 + 2 * p2);
            v.x += yv.x; v.y += yv.y;
            #pragma unroll 8
            for (int s = 0; s < 32; s++) {
                float2 pv = *(const float2*)(pA + (size_t)s * 32768 + (size_t)r * 1024 + 2 * p2);
                v.x += pv.x; v.y += pv.y;
            }
            #pragma unroll
            for (int s = 0; s < 9; s++) {
                float2 pv = *(const float2*)(pB + (size_t)s * 131072 + (size_t)r * 4096 + 3072 + 2 * p2);
                v.x += pv.x; v.y += pv.y;
            }
            l512[idx] = fmaxf(v.x, v.y);
        }
        // prefetch first P10 W tile
        if (bid < 280) {
            int ct = bid % 40, ks = bid / 40;
            int nc = 5000 - ct * 128; if (nc > 128) nc = 128;
            prefetchW(a.Wlogit, 5000, ks * 32, ct * 128, nc, wbuf);
        }
        gsync(gen);

        // ===== P10: logits5000 = l512 @ Wlogit, 280 tiles (KS=7) =====
        for (int t = bid; t < 280; t += NBLK) {
            int ct = t % 40, ks = t / 40;
            int ncols = 5000 - ct * 128; if (ncols > 128) ncols = 128;
            GPair p = {l512, 512, a.Wlogit, 5000, 512};
            gemm_tile(&p, 1, ks, 7, ct * 128, ncols,
                      pA + (size_t)ks * 160000 + ct * 128, 5000, abuf, wbuf, 1);
        }
        gsync(gen);

        // ===== P11: reduce 7 partials + local max + exp, 256 tiles =====
        for (int t = bid; t < 256; t += NBLK) {
            int b = t & 31, q = t >> 5;
            float* buf = SM;
            float* red = SM + 640;
            __syncthreads();
            float lm = -1e30f;
            for (int j0 = tid; j0 < 625; j0 += NTHR) {
                int j = q * 625 + j0;
                float v = a.blogit[j];
                #pragma unroll
                for (int s = 0; s < 7; s++)
                    v += pA[(size_t)s * 160000 + (size_t)b * 5000 + j];
                buf[j0] = v;
                lm = fmaxf(lm, v);
            }
            #pragma unroll
            for (int o = 16; o; o >>= 1) lm = fmaxf(lm, __shfl_xor_sync(0xffffffffu, lm, o));
            if ((tid & 31) == 0) red[tid >> 5] = lm;
            __syncthreads();
            float gml = red[0];
            #pragma unroll
            for (int w = 1; w < 8; w++) gml = fmaxf(gml, red[w]);
            float ls = 0.f;
            for (int j0 = tid; j0 < 625; j0 += NTHR) {
                float e = expf(buf[j0] - gml);
                expb[(size_t)b * 5000 + q * 625 + j0] = e;
                ls += e;
            }
            #pragma unroll
            for (int o = 16; o; o >>= 1) ls += __shfl_xor_sync(0xffffffffu, ls, o);
            __syncthreads();
            if ((tid & 31) == 0) red[tid >> 5] = ls;
            __syncthreads();
            if (tid == 0) {
                float tot = 0.f;
                #pragma unroll
                for (int w = 0; w < 8; w++) tot += red[w];
                ms[(b * 8 + q) * 2]     = gml;
                ms[(b * 8 + q) * 2 + 1] = tot;
            }
            __syncthreads();
        }
        // prefetch first W tile of next step's P1
        if (bid < 288) {
            int ct = bid % 24, ks = bid / 24;
            if (ct < 16) prefetchW(a.U1, 2048, ks * 32, ct * 128, 128, wbuf);
            else         prefetchW(a.Ux1, 1024, ks * 32, (ct - 16) * 128, 128, wbuf);
        }
        gsync(gen);
    }

    // ===== final 9b for step 99 =====
    for (int t = bid; t < 256; t += NBLK) {
        int b = t & 31, q = t >> 5;
        float gm = -1e30f;
        #pragma unroll
        for (int w = 0; w < 8; w++) gm = fmaxf(gm, ms[(b * 8 + w) * 2]);
        float gs = 0.f;
        #pragma unroll
        for (int w = 0; w < 8; w++)
            gs += ms[(b * 8 + w) * 2 + 1] * expf(ms[(b * 8 + w) * 2] - gm);
        float scale = expf(ms[(b * 8 + q) * 2] - gm) / gs;
        float* o = a.out + (size_t)b * 500000 + (size_t)99 * 5000 + q * 625;
        const float* src = expb + (size_t)b * 5000 + q * 625;
        for (int j0 = tid; j0 < 625; j0 += NTHR) __stcs(o + j0, src[j0] * scale);
    }

    // ===== safe barrier-counter reset =====
    __syncthreads();
    if (tid == 0) {
        unsigned r;
        asm volatile("atom.acq_rel.gpu.global.add.u32 %0, [%1], 1;"
                     : "=r"(r) : "l"(&g_bar_cnt2) : "memory");
        if (r == NBLK - 1) {
            g_bar_cnt = 0;
            g_bar_cnt2 = 0;
            __threadfence();
        }
    }
}

// ---------------- host launcher: single kernel ----------------
extern "C" void kernel_launch(void* const* d_in, const int* in_sizes, int n_in,
                              void* d_out, int out_size) {
    MKArgs a;
    a.hs     = (const float*)d_in[0];
    a.hlens  = (const int*)  d_in[1];
    a.ys     = (const int*)  d_in[2];
    a.embed  = (const float*)d_in[3];
    a.W1_W   = (const float*)d_in[4];
    a.b1_W   = (const float*)d_in[5];
    a.W1_Wx  = (const float*)d_in[6];
    a.b1_Wx  = (const float*)d_in[7];
    a.U1     = (const float*)d_in[8];
    a.Ux1    = (const float*)d_in[9];
    a.U2     = (const float*)d_in[10];
    a.b2     = (const float*)d_in[11];
    a.Wc     = (const float*)d_in[12];
    a.Ux2    = (const float*)d_in[13];
    a.bUx2   = (const float*)d_in[14];
    a.Wcx    = (const float*)d_in[15];
    a.Winit  = (const float*)d_in[16];
    a.binit  = (const float*)d_in[17];
    a.Ws     = (const float*)d_in[18];
    a.bs     = (const float*)d_in[19];
    a.Wy     = (const float*)d_in[20];
    a.We     = (const float*)d_in[21];
    a.Wlogit = (const float*)d_in[22];
    a.blogit = (const float*)d_in[23];
    a.Wenc   = (const float*)d_in[24];
    a.Wdec   = (const float*)d_in[25];
    a.out    = (float*)d_out;

    cudaFuncSetAttribute(k_mega, cudaFuncAttributeMaxDynamicSharedMemorySize, 40960);
    k_mega<<<NBLK, NTHR, 40960>>>(a);
}

// round 15
// speedup vs baseline: 1.0882x; 1.0882x over previous
#include <cuda_runtime.h>
#include <cuda_fp16.h>
#include <cstdint>
#include <math.h>

// B=32, T=500, E=1024, D=1024, EMB=256, O=5000, olen=100, A=512
#define NBLK 296
#define NTHR 256

// ---------------- scratch layout (floats) ----------------
#define OFF_EYS   ((size_t)0)          // (100,32,256)
#define OFF_SB    ((size_t)819200)     // (100,32,2048)
#define OFF_SBX   ((size_t)7372800)    // (100,32,1024)
#define OFF_ENC   ((size_t)10649600)   // (32,500,512)
#define OFF_YW    ((size_t)18841600)   // (100,32,1024) eys@Wy precomputed
#define OFF_HSUM  ((size_t)22118400)   // (32,1024)
#define OFF_H     ((size_t)22151168)
#define OFF_H1    ((size_t)22183936)
#define OFF_C     ((size_t)22216704)
#define OFF_YM    ((size_t)22249472)   // (100,32)
#define OFF_L512  ((size_t)22252672)   // (32,512)
#define OFF_MS    ((size_t)22269056)   // (32,8,2)
#define OFF_EXP   ((size_t)22269568)   // (32,5000)
#define OFF_CP    ((size_t)22429568)   // (32,9,1024) ctx partials
#define OFF_AST   ((size_t)22724480)   // (32,9,2) attn stats
#define OFF_PA    ((size_t)22725056)   // 1,179,648
#define OFF_PB    ((size_t)23904704)   // 1,179,648
#define OFF_HSH   ((size_t)25084352)   // hs in fp16: 16.384M halfs = 8.192M floats
#define SZ_TOTAL  ((size_t)33276352)

__device__ float g_scratch[SZ_TOTAL];
__device__ unsigned g_bar_cnt;
__device__ unsigned g_bar_cnt2;

// ---------------- grid barrier: REDG arrive + acquire poll ----------------
__device__ __forceinline__ void gsync(unsigned& gen) {
    gen += NBLK;
    __syncthreads();
    if (threadIdx.x == 0) {
        asm volatile("red.release.gpu.global.add.u32 [%0], 1;"
                     :: "l"(&g_bar_cnt) : "memory");
        unsigned v;
        while (true) {
            asm volatile("ld.acquire.gpu.global.u32 %0, [%1];"
                         : "=r"(v) : "l"(&g_bar_cnt) : "memory");
            if ((int)(v - gen) >= 0) break;
        }
    }
    __syncthreads();
}

__device__ __forceinline__ float sigm(float x) { return 1.f / (1.f + expf(-x)); }

// ---------------- GEMM building blocks (32 rows x 128 cols tile) ----------------
__device__ __forceinline__ void load_A(const float* A, int ldA, int k0, float* sAT) {
    int tid = threadIdx.x;
    int r = tid & 31, q = tid >> 5;
    float4 v = *(const float4*)(A + (size_t)r * ldA + k0 + q * 4);
    sAT[(q*4+0)*32 + r] = v.x; sAT[(q*4+1)*32 + r] = v.y;
    sAT[(q*4+2)*32 + r] = v.z; sAT[(q*4+3)*32 + r] = v.w;
}

__device__ __forceinline__ void load_W_async(const float* W, int ldW, int k0,
                                             int colBase, int ncols, float* sWdst) {
    unsigned sbase = (unsigned)__cvta_generic_to_shared(sWdst);
    int tid = threadIdx.x;
    #pragma unroll
    for (int v4 = 0; v4 < 4; v4++) {
        int id = tid + v4 * 256;
        int kr = id >> 5;
        int c4 = (id & 31) << 2;
        int rem = ncols - c4;
        int sz = rem >= 4 ? 16 : (rem > 0 ? rem * 4 : 0);
        int cc = (sz > 0) ? c4 : 0;
        const float* src = W + (size_t)(k0 + kr) * ldW + colBase + cc;
        unsigned d = sbase + (unsigned)((kr * 128 + c4) * 4);
        asm volatile("cp.async.cg.shared.global [%0], [%1], 16, %2;"
                     :: "r"(d), "l"(src), "r"(sz));
    }
}

// prefetch first W tile of an upcoming GEMM phase (issued during prior phase)
__device__ __forceinline__ void prefetchW(const float* W, int ldW, int k0,
                                          int colBase, int ncols, float* wbuf) {
    __syncthreads();   // ensure prior phase readers of wbuf are done
    load_W_async(W, ldW, k0, colBase, ncols, wbuf);
    asm volatile("cp.async.commit_group;" ::: "memory");
}

// packed f32x2 MMA, 8 rows x 2 cols per thread
__device__ __forceinline__ void mma_chunk(unsigned long long acc[4][2],
                                          const float* sAT, const float* sW) {
    int tid = threadIdx.x;
    int ct = tid & 63, rt = tid >> 6;
    #pragma unroll
    for (int kk = 0; kk < 32; kk++) {
        const unsigned long long* ap =
            (const unsigned long long*)(sAT + kk * 32 + rt * 8);
        unsigned long long a0 = ap[0], a1 = ap[1], a2 = ap[2], a3 = ap[3];
        float2 w = *(const float2*)(sW + kk * 128 + ct * 2);
        unsigned long long w0, w1;
        asm("mov.b64 %0, {%1,%1};" : "=l"(w0) : "f"(w.x));
        asm("mov.b64 %0, {%1,%1};" : "=l"(w1) : "f"(w.y));
        #define F2X(ac, av, wv) \
            asm("fma.rn.f32x2 %0, %1, %2, %0;" : "+l"(ac) : "l"(av), "l"(wv));
        F2X(acc[0][0], a0, w0) F2X(acc[0][1], a0, w1)
        F2X(acc[1][0], a1, w0) F2X(acc[1][1], a1, w1)
        F2X(acc[2][0], a2, w0) F2X(acc[2][1], a2, w1)
        F2X(acc[3][0], a3, w0) F2X(acc[3][1], a3, w1)
        #undef F2X
    }
}

__device__ __forceinline__ void store_tile(unsigned long long acc[4][2],
                                           float* outBase, int Ntot, int ncols) {
    int tid = threadIdx.x;
    int ct = tid & 63, rt = tid >> 6;
    int c = ct * 2;
    if (c + 2 > ncols) return;
    #pragma unroll
    for (int i = 0; i < 4; i++) {
        float lo0, hi0, lo1, hi1;
        asm("mov.b64 {%0,%1}, %2;" : "=f"(lo0), "=f"(hi0) : "l"(acc[i][0]));
        asm("mov.b64 {%0,%1}, %2;" : "=f"(lo1), "=f"(hi1) : "l"(acc[i][1]));
        float* d0 = outBase + (size_t)(rt * 8 + 2 * i) * Ntot + c;
        float* d1 = outBase + (size_t)(rt * 8 + 2 * i + 1) * Ntot + c;
        *(float2*)d0 = make_float2(lo0, lo1);
        *(float2*)d1 = make_float2(hi0, hi1);
    }
}

struct GPair { const float* A; int ldA; const float* W; int ldW; int K; };

__device__ void gemm_tile(const GPair* pr, int np, int ks, int KS,
                          int colBase, int ncols, float* outSlot, int Ntot,
                          float* abuf, float* wbuf, int wpre) {
    unsigned long long acc[4][2] = {};
    int pidx[8], koff[8];
    int m = 0, gc = 0;
    for (int p = 0; p < np; p++)
        for (int k0 = 0; k0 < pr[p].K; k0 += 32)
            if ((gc++ % KS) == ks) { pidx[m] = p; koff[m] = k0; m++; }

    __syncthreads();
    if (m > 0) {
        if (!wpre) {
            load_W_async(pr[pidx[0]].W, pr[pidx[0]].ldW, koff[0], colBase, ncols, wbuf);
            asm volatile("cp.async.commit_group;" ::: "memory");
        }
        load_A(pr[pidx[0]].A, pr[pidx[0]].ldA, koff[0], abuf);
    }
    for (int i = 0; i < m; i++) {
        asm volatile("cp.async.wait_group 0;" ::: "memory");
        __syncthreads();
        if (i + 1 < m) {
            load_W_async(pr[pidx[i+1]].W, pr[pidx[i+1]].ldW, koff[i+1],
                         colBase, ncols, wbuf + ((i + 1) & 1) * 4096);
            asm volatile("cp.async.commit_group;" ::: "memory");
            load_A(pr[pidx[i+1]].A, pr[pidx[i+1]].ldA, koff[i+1],
                   abuf + ((i + 1) & 1) * 1024);
        }
        mma_chunk(acc, abuf + (i & 1) * 1024, wbuf + (i & 1) * 4096);
    }
    store_tile(acc, outSlot, Ntot, ncols);
}

// ---------------- 64x64 tiled SGEMM (precompute) ----------
__device__ void tiled64(const float* __restrict__ A, const float* __restrict__ W,
                        const float* __restrict__ bias, float* __restrict__ C,
                        int N, int K, int act, int cx, int cy, float* USM) {
    float* sAT = USM;          // [16][68]
    float* sW  = USM + 1088;   // [16][64]
    int rowBase = cy << 6;
    int colBase = cx << 6;
    int tx = threadIdx.x & 15;
    int ty = threadIdx.x >> 4;
    float acc[4][4];
    #pragma unroll
    for (int i = 0; i < 4; i++)
        #pragma unroll
        for (int j = 0; j < 4; j++) acc[i][j] = 0.f;

    for (int k0 = 0; k0 < K; k0 += 16) {
        __syncthreads();
        {
            int r = threadIdx.x >> 2;
            int c4 = (threadIdx.x & 3) << 2;
            float4 v = *(const float4*)(A + (size_t)(rowBase + r) * K + k0 + c4);
            sAT[(c4+0)*68 + r] = v.x; sAT[(c4+1)*68 + r] = v.y;
            sAT[(c4+2)*68 + r] = v.z; sAT[(c4+3)*68 + r] = v.w;
            int kr = threadIdx.x >> 4;
            int wc = (threadIdx.x & 15) << 2;
            *(float4*)&sW[kr*64 + wc] = *(const float4*)(W + (size_t)(k0 + kr) * N + colBase + wc);
        }
        __syncthreads();
        #pragma unroll
        for (int kk = 0; kk < 16; kk++) {
            float4 a4 = *(const float4*)&sAT[kk*68 + (ty << 2)];
            float4 w4 = *(const float4*)&sW[kk*64 + (tx << 2)];
            float av[4] = {a4.x, a4.y, a4.z, a4.w};
            float wv[4] = {w4.x, w4.y, w4.z, w4.w};
            #pragma unroll
            for (int i = 0; i < 4; i++)
                #pragma unroll
                for (int j = 0; j < 4; j++)
                    acc[i][j] = fmaf(av[i], wv[j], acc[i][j]);
        }
    }
    #pragma unroll
    for (int i = 0; i < 4; i++) {
        int r = rowBase + (ty << 2) + i;
        #pragma unroll
        for (int j = 0; j < 4; j++) {
            int c = colBase + (tx << 2) + j;
            float v = acc[i][j];
            if (bias) v += bias[c];
            if (act == 1) v = tanhf(v);
            C[(size_t)r * N + c] = v;
        }
    }
}

// ---------------- megakernel ----------------
struct MKArgs {
    const float *hs, *embed, *W1_W, *b1_W, *W1_Wx, *b1_Wx, *Wenc;
    const float *U1, *Ux1, *U2, *b2, *Wc, *Ux2, *bUx2, *Wcx;
    const float *Ws, *bs, *Wy, *We, *Wlogit, *blogit, *Wdec, *Winit, *binit;
    const int *hlens, *ys;
    float* out;
};

__global__ void __launch_bounds__(NTHR, 2) k_mega(MKArgs a) {
    extern __shared__ float SM[];
    float* abuf = SM;          // 2048 floats
    float* wbuf = SM + 2048;   // 8192 floats

    float* eys  = g_scratch + OFF_EYS;
    float* sb   = g_scratch + OFF_SB;
    float* sbx  = g_scratch + OFF_SBX;
    float* enc  = g_scratch + OFF_ENC;
    float* yw   = g_scratch + OFF_YW;
    float* hsum = g_scratch + OFF_HSUM;
    float* h    = g_scratch + OFF_H;
    float* h1   = g_scratch + OFF_H1;
    float* cvec = g_scratch + OFF_C;
    float* ym   = g_scratch + OFF_YM;
    float* l512 = g_scratch + OFF_L512;
    float* ms   = g_scratch + OFF_MS;
    float* expb = g_scratch + OFF_EXP;
    float* cp   = g_scratch + OFF_CP;
    float* ast  = g_scratch + OFF_AST;
    float* pA   = g_scratch + OFF_PA;
    float* pB   = g_scratch + OFF_PB;
    __half* hsH = (__half*)(g_scratch + OFF_HSH);

    const int tid = threadIdx.x;
    const int bid = blockIdx.x;
    unsigned gen = 0;

    // ===== phase 0a: setup (ymask, eys gather, hs->fp16, hsum) =====
    if (bid == 0 && tid < 32) {
        int b = tid;
        int yl = 0;
        for (int j = 0; j < 99; j++) yl += (a.ys[b * 99 + j] != -1) ? 1 : 0;
        for (int i = 0; i < 100; i++)
            ym[i * 32 + b] = (i < yl + 1) ? 1.f : 0.f;
    }
    for (int idx4 = bid * NTHR + tid; idx4 < 204800; idx4 += NBLK * NTHR) {
        int row = idx4 >> 6;
        int i = row >> 5, b = row & 31;
        int tok = 4999;
        if (i > 0) { int v = a.ys[b * 99 + i - 1]; tok = (v < 0) ? 4999 : v; }
        int c4 = (idx4 & 63) << 2;
        *(float4*)&eys[(size_t)row * 256 + c4] =
            *(const float4*)&a.embed[(size_t)tok * 256 + c4];
    }
    // hs -> fp16 (16.384M elements, 4 per iter)
    for (int i4 = bid * NTHR + tid; i4 < 4096000; i4 += NBLK * NTHR) {
        float4 v = *((const float4*)a.hs + i4);
        __half2 p0 = __floats2half2_rn(v.x, v.y);
        __half2 p1 = __floats2half2_rn(v.z, v.w);
        ((__half2*)hsH)[(size_t)i4 * 2]     = p0;
        ((__half2*)hsH)[(size_t)i4 * 2 + 1] = p1;
    }
    for (int t = bid; t < 256; t += NBLK) {
        int b = t >> 3, ech = t & 7;
        if (tid < 128) {
            int e = ech * 128 + tid;
            const float* base = a.hs + (size_t)b * 512000 + e;
            float s0 = 0.f, s1 = 0.f;
            for (int tt = 0; tt < 500; tt += 2) {
                s0 += base[(size_t)tt * 1024];
                s1 += base[(size_t)(tt + 1) * 1024];
            }
            hsum[b * 1024 + e] = (s0 + s1) / (float)a.hlens[b];
        }
    }
    gsync(gen);

    // ===== phase 0b: sb, sbx, yW, enc via 64x64 tiles (5200 tiles) =====
    for (int t = bid; t < 5200; t += NBLK) {
        if (t < 1600)       tiled64(eys, a.W1_W, a.b1_W, sb, 2048, 256, 0,
                                    t % 32, t / 32, SM);
        else if (t < 2400)  tiled64(eys, a.W1_Wx, a.b1_Wx, sbx, 1024, 256, 0,
                                    (t - 1600) % 16, (t - 1600) / 16, SM);
        else if (t < 3200)  tiled64(eys, a.Wy, nullptr, yw, 1024, 256, 0,
                                    (t - 2400) % 16, (t - 2400) / 16, SM);
        else                tiled64(a.hs, a.Wenc, nullptr, enc, 512, 1024, 1,
                                    (t - 3200) % 8, (t - 3200) / 8, SM);
    }
    gsync(gen);

    // ===== h0 = hsum @ Winit + binit : 128 tiles =====
    for (int t = bid; t < 128; t += NBLK) {
        int ct = t & 7, ks = t >> 3;
        GPair p = {hsum, 1024, a.Winit, 1024, 1024};
        gemm_tile(&p, 1, ks, 16, ct * 128, 128,
                  pA + (size_t)ks * 32768 + ct * 128, 1024, abuf, wbuf, 0);
    }
    gsync(gen);
    for (int idx = bid * NTHR + tid; idx < 32768; idx += NBLK * NTHR) {
        float s = a.binit[idx & 1023];
        #pragma unroll 4
        for (int sI = 0; sI < 16; sI++) s += pA[(size_t)sI * 32768 + idx];
        h[idx] = s;
    }
    // prefetch first P1 W tile (step 0)
    if (bid < 288) {
        int ct = bid % 24, ks = bid / 24;
        if (ct < 16) prefetchW(a.U1, 2048, ks * 32, ct * 128, 128, wbuf);
        else         prefetchW(a.Ux1, 1024, ks * 32, (ct - 16) * 128, 128, wbuf);
    }
    gsync(gen);

    for (int step = 0; step < 100; step++) {
        // ===== P1: fused 9b(step-1) + gate1 = [h@U1 | h@Ux1], 288 tiles =====
        if (step > 0) {
            for (int t = bid; t < 256; t += NBLK) {
                int b = t & 31, q = t >> 5;
                float gm = -1e30f;
                #pragma unroll
                for (int w = 0; w < 8; w++) gm = fmaxf(gm, ms[(b * 8 + w) * 2]);
                float gs = 0.f;
                #pragma unroll
                for (int w = 0; w < 8; w++)
                    gs += ms[(b * 8 + w) * 2 + 1] * expf(ms[(b * 8 + w) * 2] - gm);
                float scale = expf(ms[(b * 8 + q) * 2] - gm) / gs;
                float* o = a.out + (size_t)b * 500000 + (size_t)(step - 1) * 5000 + q * 625;
                const float* src = expb + (size_t)b * 5000 + q * 625;
                for (int j0 = tid; j0 < 625; j0 += NTHR) __stcs(o + j0, src[j0] * scale);
            }
        }
        for (int t = bid; t < 288; t += NBLK) {
            int ct = t % 24, ks = t / 24;      // KS=12
            if (ct < 16) {
                GPair p = {h, 1024, a.U1, 2048, 1024};
                gemm_tile(&p, 1, ks, 12, ct * 128, 128,
                          pA + (size_t)ks * 98304 + ct * 128, 3072, abuf, wbuf, 1);
            } else {
                GPair p = {h, 1024, a.Ux1, 1024, 1024};
                gemm_tile(&p, 1, ks, 12, (ct - 16) * 128, 128,
                          pA + (size_t)ks * 98304 + 2048 + (ct - 16) * 128, 3072,
                          abuf, wbuf, 1);
            }
        }
        gsync(gen);

        // ===== P2: ew1 (float4, 12-slot reduce) -> h1 =====
        for (int q = bid * NTHR + tid; q < 8192; q += NBLK * NTHR) {
            int r = q >> 8, j4 = (q & 255) << 2;
            float4 pr = {0,0,0,0}, uv = {0,0,0,0}, hx = {0,0,0,0};
            #pragma unroll
            for (int s = 0; s < 12; s++) {
                const float* P = pA + (size_t)s * 98304 + (size_t)r * 3072;
                float4 v;
                v = *(const float4*)(P + j4);        pr.x+=v.x; pr.y+=v.y; pr.z+=v.z; pr.w+=v.w;
                v = *(const float4*)(P + 1024 + j4); uv.x+=v.x; uv.y+=v.y; uv.z+=v.z; uv.w+=v.w;
                v = *(const float4*)(P + 2048 + j4); hx.x+=v.x; hx.y+=v.y; hx.z+=v.z; hx.w+=v.w;
            }
            const float* x_ = sb + (size_t)step * 65536 + (size_t)r * 2048;
            float4 xa = *(const float4*)(x_ + j4);
            float4 xb = *(const float4*)(x_ + 1024 + j4);
            float4 xc = *(const float4*)(sbx + (size_t)step * 32768 + r * 1024 + j4);
            float4 ho = *(const float4*)(h + r * 1024 + j4);
            float m = ym[step * 32 + r];
            float4 res;
            #define EW1(L) { \
                float p_ = sigm(pr.L + xa.L); \
                float u_ = sigm(uv.L + xb.L); \
                float t_ = tanhf(hx.L * p_ + xc.L); \
                res.L = m * (u_ * ho.L + (1.f - u_) * t_) + (1.f - m) * ho.L; }
            EW1(x) EW1(y) EW1(z) EW1(w)
            #undef EW1
            *(float4*)(h1 + r * 1024 + j4) = res;
        }
        // prefetch first P3 W tile
        if (bid < 280) {
            int t = bid;
            if (t < 40)       prefetchW(a.Wdec, 512, (t >> 2) * 32, (t & 3) * 128, 128, wbuf);
            else if (t < 200) { int tt = t - 40;
                                prefetchW(a.U2, 2048, (tt / 16) * 32, (tt % 16) * 128, 128, wbuf); }
            else              { int tt = t - 200;
                                prefetchW(a.Ux2, 1024, (tt >> 3) * 32, (tt & 7) * 128, 128, wbuf); }
        }
        gsync(gen);

        // ===== P3: dq + h1@U2 + h1@Ux2 partials, 280 tiles (KS=10) =====
        for (int t = bid; t < 280; t += NBLK) {
            if (t < 40) {
                int ct = t & 3, ks = t >> 2;
                GPair p = {h1, 1024, a.Wdec, 512, 1024};
                gemm_tile(&p, 1, ks, 10, ct * 128, 128,
                          pB + (size_t)ks * 16384 + ct * 128, 512, abuf, wbuf, 1);
            } else if (t < 200) {
                int tt = t - 40, ct = tt % 16, ks = tt / 16;
                GPair p = {h1, 1024, a.U2, 2048, 1024};
                gemm_tile(&p, 1, ks, 10, ct * 128, 128,
                          pA + (size_t)ks * 98304 + ct * 128, 3072, abuf, wbuf, 1);
            } else {
                int tt = t - 200, ct = tt & 7, ks = tt >> 3;
                GPair p = {h1, 1024, a.Ux2, 1024, 1024};
                gemm_tile(&p, 1, ks, 10, ct * 128, 128,
                          pA + (size_t)ks * 98304 + 2048 + ct * 128, 3072, abuf, wbuf, 1);
            }
        }
        gsync(gen);

        // ===== P4: online-softmax attention, 288 tiles (b x 9 t-chunks of 56) =====
        for (int t = bid; t < 288; t += NBLK) {
            int b = t & 31, tch = t >> 5;
            __syncthreads();
            float* dqs = SM;           // 512
            float* sc  = SM + 512;     // 56
            for (int j = tid; j < 512; j += NTHR) {
                float s = 0.f;
                #pragma unroll
                for (int sI = 0; sI < 10; sI++)
                    s += pB[(size_t)sI * 16384 + b * 512 + j];
                dqs[j] = tanhf(s);
            }
            __syncthreads();
            int t0 = tch * 56;
            int tn = 500 - t0; if (tn > 56) tn = 56;
            int w = tid >> 5, l = tid & 31;
            int hl = a.hlens[b];
            for (int tt = w; tt < tn; tt += 8) {
                const float* row = enc + ((size_t)b * 500 + t0 + tt) * 512;
                float s = 0.f;
                #pragma unroll
                for (int qq = 0; qq < 16; qq++)
                    s = fmaf(row[l + qq * 32], dqs[l + qq * 32], s);
                #pragma unroll
                for (int o = 16; o; o >>= 1) s += __shfl_xor_sync(0xffffffffu, s, o);
                if (l == 0) sc[tt] = (t0 + tt < hl) ? s : -1e9f;
            }
            __syncthreads();
            if (tid < 32) {
                float mloc = -1e30f;
                for (int i = l; i < tn; i += 32) mloc = fmaxf(mloc, sc[i]);
                #pragma unroll
                for (int o = 16; o; o >>= 1) mloc = fmaxf(mloc, __shfl_xor_sync(0xffffffffu, mloc, o));
                float ssum = 0.f;
                for (int i = l; i < tn; i += 32) {
                    float e = expf(sc[i] - mloc);
                    sc[i] = e;
                    ssum += e;
                }
                #pragma unroll
                for (int o = 16; o; o >>= 1) ssum += __shfl_xor_sync(0xffffffffu, ssum, o);
                if (l == 0) {
                    ast[(b * 9 + tch) * 2]     = mloc;
                    ast[(b * 9 + tch) * 2 + 1] = ssum;
                }
            }
            __syncthreads();
            // ctx partial: 256 threads x 4 e-cols, fp16 hs streamed evict-first
            int e0 = tid * 4;
            float4 acc = {0,0,0,0};
            const __half* hb = hsH + (size_t)b * 512000 + (size_t)t0 * 1024 + e0;
            #pragma unroll 4
            for (int tt = 0; tt < tn; tt++) {
                float wg = sc[tt];
                float2 raw = __ldcs((const float2*)(hb + (size_t)tt * 1024));
                __half2 h01 = ((__half2*)&raw)[0];
                __half2 h23 = ((__half2*)&raw)[1];
                float2 f01 = __half22float2(h01);
                float2 f23 = __half22float2(h23);
                acc.x = fmaf(wg, f01.x, acc.x);
                acc.y = fmaf(wg, f01.y, acc.y);
                acc.z = fmaf(wg, f23.x, acc.z);
                acc.w = fmaf(wg, f23.y, acc.w);
            }
            *(float4*)(cp + (size_t)(b * 9 + tch) * 1024 + e0) = acc;
            __syncthreads();
        }
        gsync(gen);

        // ===== P5: ctx combine -> cvec, 128 tiles (b x 4 e-chunks of 256) =====
        for (int t = bid; t < 128; t += NBLK) {
            int b = t & 31, ech = t >> 5;
            float M = -1e30f;
            #pragma unroll
            for (int ch = 0; ch < 9; ch++) M = fmaxf(M, ast[(b * 9 + ch) * 2]);
            float Z = 0.f;
            float scl[9];
            #pragma unroll
            for (int ch = 0; ch < 9; ch++) {
                scl[ch] = expf(ast[(b * 9 + ch) * 2] - M);
                Z += ast[(b * 9 + ch) * 2 + 1] * scl[ch];
            }
            float inv = 1.f / Z;
            int e = ech * 256 + tid;
            float s = 0.f;
            #pragma unroll
            for (int ch = 0; ch < 9; ch++)
                s = fmaf(cp[(size_t)(b * 9 + ch) * 1024 + e], scl[ch], s);
            cvec[b * 1024 + e] = s * inv;
        }
        // prefetch first P6 W tile
        if (bid < 288) {
            int t = bid;
            if (t < 144)      prefetchW(a.Wc, 2048, (t / 16) * 32, (t % 16) * 128, 128, wbuf);
            else if (t < 216) { int tt = t - 144;
                                prefetchW(a.Wcx, 1024, (tt >> 3) * 32, (tt & 7) * 128, 128, wbuf); }
            else              { int tt = t - 216;
                                prefetchW(a.We, 1024, (tt >> 3) * 32, (tt & 7) * 128, 128, wbuf); }
        }
        gsync(gen);

        // ===== P6: c@Wc | c@Wcx | c@We, 288 tiles (KS=9) =====
        for (int t = bid; t < 288; t += NBLK) {
            if (t < 144) {
                int ct = t % 16, ks = t / 16;
                GPair p = {cvec, 1024, a.Wc, 2048, 1024};
                gemm_tile(&p, 1, ks, 9, ct * 128, 128,
                          pB + (size_t)ks * 131072 + ct * 128, 4096, abuf, wbuf, 1);
            } else if (t < 216) {
                int tt = t - 144, ct = tt & 7, ks = tt >> 3;
                GPair p = {cvec, 1024, a.Wcx, 1024, 1024};
                gemm_tile(&p, 1, ks, 9, ct * 128, 128,
                          pB + (size_t)ks * 131072 + 2048 + ct * 128, 4096, abuf, wbuf, 1);
            } else {
                int tt = t - 216, ct = tt & 7, ks = tt >> 3;
                GPair p = {cvec, 1024, a.We, 1024, 1024};
                gemm_tile(&p, 1, ks, 9, ct * 128, 128,
                          pB + (size_t)ks * 131072 + 3072 + ct * 128, 4096, abuf, wbuf, 1);
            }
        }
        gsync(gen);

        // ===== P7: ew2 (float4) -> h (=h2) =====
        for (int q = bid * NTHR + tid; q < 8192; q += NBLK * NTHR) {
            int r = q >> 8, j4 = (q & 255) << 2;
            float4 pr = {0,0,0,0}, uv = {0,0,0,0}, hx = {0,0,0,0}, cx = {0,0,0,0};
            #pragma unroll
            for (int s = 0; s < 10; s++) {
                const float* P = pA + (size_t)s * 98304 + (size_t)r * 3072;
                float4 v;
                v = *(const float4*)(P + j4);        pr.x+=v.x; pr.y+=v.y; pr.z+=v.z; pr.w+=v.w;
                v = *(const float4*)(P + 1024 + j4); uv.x+=v.x; uv.y+=v.y; uv.z+=v.z; uv.w+=v.w;
                v = *(const float4*)(P + 2048 + j4); hx.x+=v.x; hx.y+=v.y; hx.z+=v.z; hx.w+=v.w;
            }
            #pragma unroll
            for (int s = 0; s < 9; s++) {
                const float* P = pB + (size_t)s * 131072 + (size_t)r * 4096;
                float4 v;
                v = *(const float4*)(P + j4);        pr.x+=v.x; pr.y+=v.y; pr.z+=v.z; pr.w+=v.w;
                v = *(const float4*)(P + 1024 + j4); uv.x+=v.x; uv.y+=v.y; uv.z+=v.z; uv.w+=v.w;
                v = *(const float4*)(P + 2048 + j4); cx.x+=v.x; cx.y+=v.y; cx.z+=v.z; cx.w+=v.w;
            }
            float4 ba = *(const float4*)(a.b2 + j4);
            float4 bb = *(const float4*)(a.b2 + 1024 + j4);
            float4 bu = *(const float4*)(a.bUx2 + j4);
            float4 h1v = *(const float4*)(h1 + r * 1024 + j4);
            float m = ym[step * 32 + r];
            float4 res;
            #define EW2(L) { \
                float p_ = sigm(pr.L + ba.L); \
                float u_ = sigm(uv.L + bb.L); \
                float t_ = tanhf((hx.L + bu.L) * p_ + cx.L); \
                res.L = m * (u_ * h1v.L + (1.f - u_) * t_) + (1.f - m) * h1v.L; }
            EW2(x) EW2(y) EW2(z) EW2(w)
            #undef EW2
            *(float4*)(h + r * 1024 + j4) = res;
        }
        // prefetch P8 W tile (m=1 phase)
        if (bid < 256)
            prefetchW(a.Ws, 1024, (bid >> 3) * 32, (bid & 7) * 128, 128, wbuf);
        gsync(gen);

        // ===== P8: h2@Ws, 256 tiles (KS=32, m=1, W prefetched) =====
        for (int t = bid; t < 256; t += NBLK) {
            int ct = t & 7, ks = t >> 3;
            GPair p = {h, 1024, a.Ws, 1024, 1024};
            gemm_tile(&p, 1, ks, 32, ct * 128, 128,
                      pA + (size_t)ks * 32768 + ct * 128, 1024, abuf, wbuf, 1);
        }
        gsync(gen);

        // ===== P9: pool (32 Ws slots + 9 We slots + yW + bs, pairmax) -> l512 =====
        for (int idx = bid * NTHR + tid; idx < 16384; idx += NBLK * NTHR) {
            int r = idx >> 9, p2 = idx & 511;
            float2 v = *(const float2*)(a.bs + 2 * p2);
            float2 yv = *(const float2*)(yw + (size_t)step * 32768 + r * 1024 + 2 * p2);
            v.x += yv.x; v.y += yv.y;
            #pragma unroll 8
            for (int s = 0; s < 32; s++) {
                float2 pv = *(const float2*)(pA + (size_t)s * 32768 + (size_t)r * 1024 + 2 * p2);
                v.x += pv.x; v.y += pv.y;
            }
            #pragma unroll
            for (int s = 0; s < 9; s++) {
                float2 pv = *(const float2*)(pB + (size_t)s * 131072 + (size_t)r * 4096 + 3072 + 2 * p2);
                v.x += pv.x; v.y += pv.y;
            }
            l512[idx] = fmaxf(v.x, v.y);
        }
        // prefetch first P10 W tile
        if (bid < 280) {
            int ct = bid % 40, ks = bid / 40;
            int nc = 5000 - ct * 128; if (nc > 128) nc = 128;
            prefetchW(a.Wlogit, 5000, ks * 32, ct * 128, nc, wbuf);
        }
        gsync(gen);

        // ===== P10: logits5000 = l512 @ Wlogit, 280 tiles (KS=7) =====
        for (int t = bid; t < 280; t += NBLK) {
            int ct = t % 40, ks = t / 40;
            int ncols = 5000 - ct * 128; if (ncols > 128) ncols = 128;
            GPair p = {l512, 512, a.Wlogit, 5000, 512};
            gemm_tile(&p, 1, ks, 7, ct * 128, ncols,
                      pA + (size_t)ks * 160000 + ct * 128, 5000, abuf, wbuf, 1);
        }
        gsync(gen);

        // ===== P11: reduce 7 partials + local max + exp, 256 tiles =====
        for (int t = bid; t < 256; t += NBLK) {
            int b = t & 31, q = t >> 5;
            float* buf = SM;
            float* red = SM + 640;
            __syncthreads();
            float lm = -1e30f;
            for (int j0 = tid; j0 < 625; j0 += NTHR) {
                int j = q * 625 + j0;
                float v = a.blogit[j];
                #pragma unroll
                for (int s = 0; s < 7; s++)
                    v += pA[(size_t)s * 160000 + (size_t)b * 5000 + j];
                buf[j0] = v;
                lm = fmaxf(lm, v);
            }
            #pragma unroll
            for (int o = 16; o; o >>= 1) lm = fmaxf(lm, __shfl_xor_sync(0xffffffffu, lm, o));
            if ((tid & 31) == 0) red[tid >> 5] = lm;
            __syncthreads();
            float gml = red[0];
            #pragma unroll
            for (int w = 1; w < 8; w++) gml = fmaxf(gml, red[w]);
            float ls = 0.f;
            for (int j0 = tid; j0 < 625; j0 += NTHR) {
                float e = expf(buf[j0] - gml);
                expb[(size_t)b * 5000 + q * 625 + j0] = e;
                ls += e;
            }
            #pragma unroll
            for (int o = 16; o; o >>= 1) ls += __shfl_xor_sync(0xffffffffu, ls, o);
            __syncthreads();
            if ((tid & 31) == 0) red[tid >> 5] = ls;
            __syncthreads();
            if (tid == 0) {
                float tot = 0.f;
                #pragma unroll
                for (int w = 0; w < 8; w++) tot += red[w];
                ms[(b * 8 + q) * 2]     = gml;
                ms[(b * 8 + q) * 2 + 1] = tot;
            }
            __syncthreads();
        }
        // prefetch first W tile of next step's P1
        if (bid < 288) {
            int ct = bid % 24, ks = bid / 24;
            if (ct < 16) prefetchW(a.U1, 2048, ks * 32, ct * 128, 128, wbuf);
            else         prefetchW(a.Ux1, 1024, ks * 32, (ct - 16) * 128, 128, wbuf);
        }
        gsync(gen);
    }

    // ===== final 9b for step 99 =====
    for (int t = bid; t < 256; t += NBLK) {
        int b = t & 31, q = t >> 5;
        float gm = -1e30f;
        #pragma unroll
        for (int w = 0; w < 8; w++) gm = fmaxf(gm, ms[(b * 8 + w) * 2]);
        float gs = 0.f;
        #pragma unroll
        for (int w = 0; w < 8; w++)
            gs += ms[(b * 8 + w) * 2 + 1] * expf(ms[(b * 8 + w) * 2] - gm);
        float scale = expf(ms[(b * 8 + q) * 2] - gm) / gs;
        float* o = a.out + (size_t)b * 500000 + (size_t)99 * 5000 + q * 625;
        const float* src = expb + (size_t)b * 5000 + q * 625;
        for (int j0 = tid; j0 < 625; j0 += NTHR) __stcs(o + j0, src[j0] * scale);
    }

    // ===== safe barrier-counter reset =====
    __syncthreads();
    if (tid == 0) {
        unsigned r;
        asm volatile("atom.acq_rel.gpu.global.add.u32 %0, [%1], 1;"
                     : "=r"(r) : "l"(&g_bar_cnt2) : "memory");
        if (r == NBLK - 1) {
            g_bar_cnt = 0;
            g_bar_cnt2 = 0;
            __threadfence();
        }
    }
}

// ---------------- host launcher: single kernel ----------------
extern "C" void kernel_launch(void* const* d_in, const int* in_sizes, int n_in,
                              void* d_out, int out_size) {
    MKArgs a;
    a.hs     = (const float*)d_in[0];
    a.hlens  = (const int*)  d_in[1];
    a.ys     = (const int*)  d_in[2];
    a.embed  = (const float*)d_in[3];
    a.W1_W   = (const float*)d_in[4];
    a.b1_W   = (const float*)d_in[5];
    a.W1_Wx  = (const float*)d_in[6];
    a.b1_Wx  = (const float*)d_in[7];
    a.U1     = (const float*)d_in[8];
    a.Ux1    = (const float*)d_in[9];
    a.U2     = (const float*)d_in[10];
    a.b2     = (const float*)d_in[11];
    a.Wc     = (const float*)d_in[12];
    a.Ux2    = (const float*)d_in[13];
    a.bUx2   = (const float*)d_in[14];
    a.Wcx    = (const float*)d_in[15];
    a.Winit  = (const float*)d_in[16];
    a.binit  = (const float*)d_in[17];
    a.Ws     = (const float*)d_in[18];
    a.bs     = (const float*)d_in[19];
    a.Wy     = (const float*)d_in[20];
    a.We     = (const float*)d_in[21];
    a.Wlogit = (const float*)d_in[22];
    a.blogit = (const float*)d_in[23];
    a.Wenc   = (const float*)d_in[24];
    a.Wdec   = (const float*)d_in[25];
    a.out    = (float*)d_out;

    cudaFuncSetAttribute(k_mega, cudaFuncAttributeMaxDynamicSharedMemorySize, 40960);
    k_mega<<<NBLK, NTHR, 40960>>>(a);
}

// round 16
// speedup vs baseline: 1.1114x; 1.0213x over previous
#include <cuda_runtime.h>
#include <cuda_fp16.h>
#include <cstdint>
#include <math.h>

// B=32, T=500, E=1024, D=1024, EMB=256, O=5000, olen=100, A=512
#define NBLK 296
#define NTHR 256

// ---------------- scratch layout (floats) ----------------
#define OFF_EYS   ((size_t)0)          // (100,32,256)
#define OFF_SB    ((size_t)819200)     // (100,32,2048)
#define OFF_SBX   ((size_t)7372800)    // (100,32,1024)
#define OFF_ENC   ((size_t)10649600)   // (32,500,512)
#define OFF_YW    ((size_t)18841600)   // (100,32,1024) eys@Wy precomputed
#define OFF_HSUM  ((size_t)22118400)   // (32,1024)
#define OFF_H     ((size_t)22151168)
#define OFF_H1    ((size_t)22183936)
#define OFF_C     ((size_t)22216704)
#define OFF_YM    ((size_t)22249472)   // (100,32)
#define OFF_L512  ((size_t)22252672)   // (32,512)
#define OFF_MS    ((size_t)22269056)   // (32,8,2)
#define OFF_EXP   ((size_t)22269568)   // (32,5000)
#define OFF_CP    ((size_t)22429568)   // (32,9,1024) ctx partials
#define OFF_AST   ((size_t)22724480)   // (32,9,2) attn stats
#define OFF_PA    ((size_t)22725056)   // 1,179,648
#define OFF_PB    ((size_t)23904704)   // 1,179,648
#define OFF_HSH   ((size_t)25084352)   // hs in fp16: 16.384M halfs = 8.192M floats
#define SZ_TOTAL  ((size_t)33276352)

__device__ float g_scratch[SZ_TOTAL];
__device__ unsigned g_bar_cnt;
__device__ unsigned g_bar_cnt2;

// ---------------- grid barrier: REDG arrive + acquire poll ----------------
__device__ __forceinline__ void gsync(unsigned& gen) {
    gen += NBLK;
    __syncthreads();
    if (threadIdx.x == 0) {
        asm volatile("red.release.gpu.global.add.u32 [%0], 1;"
                     :: "l"(&g_bar_cnt) : "memory");
        unsigned v;
        while (true) {
            asm volatile("ld.acquire.gpu.global.u32 %0, [%1];"
                         : "=r"(v) : "l"(&g_bar_cnt) : "memory");
            if ((int)(v - gen) >= 0) break;
        }
    }
    __syncthreads();
}

__device__ __forceinline__ float sigm(float x) { return 1.f / (1.f + expf(-x)); }

// ---------------- GEMM building blocks (32 rows x 128 cols tile) ----------------
__device__ __forceinline__ void load_A(const float* A, int ldA, int k0, float* sAT) {
    int tid = threadIdx.x;
    int r = tid & 31, q = tid >> 5;
    float4 v = *(const float4*)(A + (size_t)r * ldA + k0 + q * 4);
    sAT[(q*4+0)*32 + r] = v.x; sAT[(q*4+1)*32 + r] = v.y;
    sAT[(q*4+2)*32 + r] = v.z; sAT[(q*4+3)*32 + r] = v.w;
}

// cp.async with L2 evict_last policy: weights (56 MB total) stay L2-resident
// across the step loop while hs/enc streams evict first.
__device__ __forceinline__ void load_W_async(const float* W, int ldW, int k0,
                                             int colBase, int ncols, float* sWdst) {
    unsigned sbase = (unsigned)__cvta_generic_to_shared(sWdst);
    int tid = threadIdx.x;
    #pragma unroll
    for (int v4 = 0; v4 < 4; v4++) {
        int id = tid + v4 * 256;
        int kr = id >> 5;
        int c4 = (id & 31) << 2;
        int rem = ncols - c4;
        int sz = rem >= 4 ? 16 : (rem > 0 ? rem * 4 : 0);
        int cc = (sz > 0) ? c4 : 0;
        const float* src = W + (size_t)(k0 + kr) * ldW + colBase + cc;
        unsigned d = sbase + (unsigned)((kr * 128 + c4) * 4);
        asm volatile(
            "{\n\t"
            ".reg .b64 pol;\n\t"
            "createpolicy.fractional.L2::evict_last.b64 pol, 1.0;\n\t"
            "cp.async.cg.shared.global.L2::cache_hint [%0], [%1], 16, %2, pol;\n\t"
            "}"
            :: "r"(d), "l"(src), "r"(sz));
    }
}

// prefetch first W tile of an upcoming GEMM phase (issued during prior phase)
__device__ __forceinline__ void prefetchW(const float* W, int ldW, int k0,
                                          int colBase, int ncols, float* wbuf) {
    __syncthreads();   // ensure prior phase readers of wbuf are done
    load_W_async(W, ldW, k0, colBase, ncols, wbuf);
    asm volatile("cp.async.commit_group;" ::: "memory");
}

// packed f32x2 MMA, 8 rows x 2 cols per thread
__device__ __forceinline__ void mma_chunk(unsigned long long acc[4][2],
                                          const float* sAT, const float* sW) {
    int tid = threadIdx.x;
    int ct = tid & 63, rt = tid >> 6;
    #pragma unroll
    for (int kk = 0; kk < 32; kk++) {
        const unsigned long long* ap =
            (const unsigned long long*)(sAT + kk * 32 + rt * 8);
        unsigned long long a0 = ap[0], a1 = ap[1], a2 = ap[2], a3 = ap[3];
        float2 w = *(const float2*)(sW + kk * 128 + ct * 2);
        unsigned long long w0, w1;
        asm("mov.b64 %0, {%1,%1};" : "=l"(w0) : "f"(w.x));
        asm("mov.b64 %0, {%1,%1};" : "=l"(w1) : "f"(w.y));
        #define F2X(ac, av, wv) \
            asm("fma.rn.f32x2 %0, %1, %2, %0;" : "+l"(ac) : "l"(av), "l"(wv));
        F2X(acc[0][0], a0, w0) F2X(acc[0][1], a0, w1)
        F2X(acc[1][0], a1, w0) F2X(acc[1][1], a1, w1)
        F2X(acc[2][0], a2, w0) F2X(acc[2][1], a2, w1)
        F2X(acc[3][0], a3, w0) F2X(acc[3][1], a3, w1)
        #undef F2X
    }
}

__device__ __forceinline__ void store_tile(unsigned long long acc[4][2],
                                           float* outBase, int Ntot, int ncols) {
    int tid = threadIdx.x;
    int ct = tid & 63, rt = tid >> 6;
    int c = ct * 2;
    if (c + 2 > ncols) return;
    #pragma unroll
    for (int i = 0; i < 4; i++) {
        float lo0, hi0, lo1, hi1;
        asm("mov.b64 {%0,%1}, %2;" : "=f"(lo0), "=f"(hi0) : "l"(acc[i][0]));
        asm("mov.b64 {%0,%1}, %2;" : "=f"(lo1), "=f"(hi1) : "l"(acc[i][1]));
        float* d0 = outBase + (size_t)(rt * 8 + 2 * i) * Ntot + c;
        float* d1 = outBase + (size_t)(rt * 8 + 2 * i + 1) * Ntot + c;
        *(float2*)d0 = make_float2(lo0, lo1);
        *(float2*)d1 = make_float2(hi0, hi1);
    }
}

struct GPair { const float* A; int ldA; const float* W; int ldW; int K; };

__device__ void gemm_tile(const GPair* pr, int np, int ks, int KS,
                          int colBase, int ncols, float* outSlot, int Ntot,
                          float* abuf, float* wbuf, int wpre) {
    unsigned long long acc[4][2] = {};
    int pidx[8], koff[8];
    int m = 0, gc = 0;
    for (int p = 0; p < np; p++)
        for (int k0 = 0; k0 < pr[p].K; k0 += 32)
            if ((gc++ % KS) == ks) { pidx[m] = p; koff[m] = k0; m++; }

    __syncthreads();
    if (m > 0) {
        if (!wpre) {
            load_W_async(pr[pidx[0]].W, pr[pidx[0]].ldW, koff[0], colBase, ncols, wbuf);
            asm volatile("cp.async.commit_group;" ::: "memory");
        }
        load_A(pr[pidx[0]].A, pr[pidx[0]].ldA, koff[0], abuf);
    }
    for (int i = 0; i < m; i++) {
        asm volatile("cp.async.wait_group 0;" ::: "memory");
        __syncthreads();
        if (i + 1 < m) {
            load_W_async(pr[pidx[i+1]].W, pr[pidx[i+1]].ldW, koff[i+1],
                         colBase, ncols, wbuf + ((i + 1) & 1) * 4096);
            asm volatile("cp.async.commit_group;" ::: "memory");
            load_A(pr[pidx[i+1]].A, pr[pidx[i+1]].ldA, koff[i+1],
                   abuf + ((i + 1) & 1) * 1024);
        }
        mma_chunk(acc, abuf + (i & 1) * 1024, wbuf + (i & 1) * 4096);
    }
    store_tile(acc, outSlot, Ntot, ncols);
}

// ---------------- 64x64 tiled SGEMM (precompute) ----------
__device__ void tiled64(const float* __restrict__ A, const float* __restrict__ W,
                        const float* __restrict__ bias, float* __restrict__ C,
                        int N, int K, int act, int cx, int cy, float* USM) {
    float* sAT = USM;          // [16][68]
    float* sW  = USM + 1088;   // [16][64]
    int rowBase = cy << 6;
    int colBase = cx << 6;
    int tx = threadIdx.x & 15;
    int ty = threadIdx.x >> 4;
    float acc[4][4];
    #pragma unroll
    for (int i = 0; i < 4; i++)
        #pragma unroll
        for (int j = 0; j < 4; j++) acc[i][j] = 0.f;

    for (int k0 = 0; k0 < K; k0 += 16) {
        __syncthreads();
        {
            int r = threadIdx.x >> 2;
            int c4 = (threadIdx.x & 3) << 2;
            float4 v = *(const float4*)(A + (size_t)(rowBase + r) * K + k0 + c4);
            sAT[(c4+0)*68 + r] = v.x; sAT[(c4+1)*68 + r] = v.y;
            sAT[(c4+2)*68 + r] = v.z; sAT[(c4+3)*68 + r] = v.w;
            int kr = threadIdx.x >> 4;
            int wc = (threadIdx.x & 15) << 2;
            *(float4*)&sW[kr*64 + wc] = *(const float4*)(W + (size_t)(k0 + kr) * N + colBase + wc);
        }
        __syncthreads();
        #pragma unroll
        for (int kk = 0; kk < 16; kk++) {
            float4 a4 = *(const float4*)&sAT[kk*68 + (ty << 2)];
            float4 w4 = *(const float4*)&sW[kk*64 + (tx << 2)];
            float av[4] = {a4.x, a4.y, a4.z, a4.w};
            float wv[4] = {w4.x, w4.y, w4.z, w4.w};
            #pragma unroll
            for (int i = 0; i < 4; i++)
                #pragma unroll
                for (int j = 0; j < 4; j++)
                    acc[i][j] = fmaf(av[i], wv[j], acc[i][j]);
        }
    }
    #pragma unroll
    for (int i = 0; i < 4; i++) {
        int r = rowBase + (ty << 2) + i;
        #pragma unroll
        for (int j = 0; j < 4; j++) {
            int c = colBase + (tx << 2) + j;
            float v = acc[i][j];
            if (bias) v += bias[c];
            if (act == 1) v = tanhf(v);
            C[(size_t)r * N + c] = v;
        }
    }
}

// ---------------- megakernel ----------------
struct MKArgs {
    const float *hs, *embed, *W1_W, *b1_W, *W1_Wx, *b1_Wx, *Wenc;
    const float *U1, *Ux1, *U2, *b2, *Wc, *Ux2, *bUx2, *Wcx;
    const float *Ws, *bs, *Wy, *We, *Wlogit, *blogit, *Wdec, *Winit, *binit;
    const int *hlens, *ys;
    float* out;
};

__global__ void __launch_bounds__(NTHR, 2) k_mega(MKArgs a) {
    extern __shared__ float SM[];
    float* abuf = SM;          // 2048 floats
    float* wbuf = SM + 2048;   // 8192 floats

    float* eys  = g_scratch + OFF_EYS;
    float* sb   = g_scratch + OFF_SB;
    float* sbx  = g_scratch + OFF_SBX;
    float* enc  = g_scratch + OFF_ENC;
    float* yw   = g_scratch + OFF_YW;
    float* hsum = g_scratch + OFF_HSUM;
    float* h    = g_scratch + OFF_H;
    float* h1   = g_scratch + OFF_H1;
    float* cvec = g_scratch + OFF_C;
    float* ym   = g_scratch + OFF_YM;
    float* l512 = g_scratch + OFF_L512;
    float* ms   = g_scratch + OFF_MS;
    float* expb = g_scratch + OFF_EXP;
    float* cp   = g_scratch + OFF_CP;
    float* ast  = g_scratch + OFF_AST;
    float* pA   = g_scratch + OFF_PA;
    float* pB   = g_scratch + OFF_PB;
    __half* hsH = (__half*)(g_scratch + OFF_HSH);

    const int tid = threadIdx.x;
    const int bid = blockIdx.x;
    unsigned gen = 0;

    // ===== phase 0a: setup (ymask, eys gather, hs->fp16, hsum) =====
    if (bid == 0 && tid < 32) {
        int b = tid;
        int yl = 0;
        for (int j = 0; j < 99; j++) yl += (a.ys[b * 99 + j] != -1) ? 1 : 0;
        for (int i = 0; i < 100; i++)
            ym[i * 32 + b] = (i < yl + 1) ? 1.f : 0.f;
    }
    for (int idx4 = bid * NTHR + tid; idx4 < 204800; idx4 += NBLK * NTHR) {
        int row = idx4 >> 6;
        int i = row >> 5, b = row & 31;
        int tok = 4999;
        if (i > 0) { int v = a.ys[b * 99 + i - 1]; tok = (v < 0) ? 4999 : v; }
        int c4 = (idx4 & 63) << 2;
        *(float4*)&eys[(size_t)row * 256 + c4] =
            *(const float4*)&a.embed[(size_t)tok * 256 + c4];
    }
    // hs -> fp16 (16.384M elements, 4 per iter)
    for (int i4 = bid * NTHR + tid; i4 < 4096000; i4 += NBLK * NTHR) {
        float4 v = *((const float4*)a.hs + i4);
        __half2 p0 = __floats2half2_rn(v.x, v.y);
        __half2 p1 = __floats2half2_rn(v.z, v.w);
        ((__half2*)hsH)[(size_t)i4 * 2]     = p0;
        ((__half2*)hsH)[(size_t)i4 * 2 + 1] = p1;
    }
    for (int t = bid; t < 256; t += NBLK) {
        int b = t >> 3, ech = t & 7;
        if (tid < 128) {
            int e = ech * 128 + tid;
            const float* base = a.hs + (size_t)b * 512000 + e;
            float s0 = 0.f, s1 = 0.f;
            for (int tt = 0; tt < 500; tt += 2) {
                s0 += base[(size_t)tt * 1024];
                s1 += base[(size_t)(tt + 1) * 1024];
            }
            hsum[b * 1024 + e] = (s0 + s1) / (float)a.hlens[b];
        }
    }
    gsync(gen);

    // ===== phase 0b: sb, sbx, yW, enc via 64x64 tiles (5200 tiles) =====
    for (int t = bid; t < 5200; t += NBLK) {
        if (t < 1600)       tiled64(eys, a.W1_W, a.b1_W, sb, 2048, 256, 0,
                                    t % 32, t / 32, SM);
        else if (t < 2400)  tiled64(eys, a.W1_Wx, a.b1_Wx, sbx, 1024, 256, 0,
                                    (t - 1600) % 16, (t - 1600) / 16, SM);
        else if (t < 3200)  tiled64(eys, a.Wy, nullptr, yw, 1024, 256, 0,
                                    (t - 2400) % 16, (t - 2400) / 16, SM);
        else                tiled64(a.hs, a.Wenc, nullptr, enc, 512, 1024, 1,
                                    (t - 3200) % 8, (t - 3200) / 8, SM);
    }
    gsync(gen);

    // ===== h0 = hsum @ Winit + binit : 128 tiles =====
    for (int t = bid; t < 128; t += NBLK) {
        int ct = t & 7, ks = t >> 3;
        GPair p = {hsum, 1024, a.Winit, 1024, 1024};
        gemm_tile(&p, 1, ks, 16, ct * 128, 128,
                  pA + (size_t)ks * 32768 + ct * 128, 1024, abuf, wbuf, 0);
    }
    gsync(gen);
    for (int idx = bid * NTHR + tid; idx < 32768; idx += NBLK * NTHR) {
        float s = a.binit[idx & 1023];
        #pragma unroll 4
        for (int sI = 0; sI < 16; sI++) s += pA[(size_t)sI * 32768 + idx];
        h[idx] = s;
    }
    // prefetch first P1 W tile (step 0)
    if (bid < 288) {
        int ct = bid % 24, ks = bid / 24;
        if (ct < 16) prefetchW(a.U1, 2048, ks * 32, ct * 128, 128, wbuf);
        else         prefetchW(a.Ux1, 1024, ks * 32, (ct - 16) * 128, 128, wbuf);
    }
    gsync(gen);

    for (int step = 0; step < 100; step++) {
        // ===== P1: fused 9b(step-1) + gate1 = [h@U1 | h@Ux1], 288 tiles =====
        if (step > 0) {
            for (int t = bid; t < 256; t += NBLK) {
                int b = t & 31, q = t >> 5;
                float gm = -1e30f;
                #pragma unroll
                for (int w = 0; w < 8; w++) gm = fmaxf(gm, ms[(b * 8 + w) * 2]);
                float gs = 0.f;
                #pragma unroll
                for (int w = 0; w < 8; w++)
                    gs += ms[(b * 8 + w) * 2 + 1] * expf(ms[(b * 8 + w) * 2] - gm);
                float scale = expf(ms[(b * 8 + q) * 2] - gm) / gs;
                float* o = a.out + (size_t)b * 500000 + (size_t)(step - 1) * 5000 + q * 625;
                const float* src = expb + (size_t)b * 5000 + q * 625;
                for (int j0 = tid; j0 < 625; j0 += NTHR) __stcs(o + j0, src[j0] * scale);
            }
        }
        for (int t = bid; t < 288; t += NBLK) {
            int ct = t % 24, ks = t / 24;      // KS=12
            if (ct < 16) {
                GPair p = {h, 1024, a.U1, 2048, 1024};
                gemm_tile(&p, 1, ks, 12, ct * 128, 128,
                          pA + (size_t)ks * 98304 + ct * 128, 3072, abuf, wbuf, 1);
            } else {
                GPair p = {h, 1024, a.Ux1, 1024, 1024};
                gemm_tile(&p, 1, ks, 12, (ct - 16) * 128, 128,
                          pA + (size_t)ks * 98304 + 2048 + (ct - 16) * 128, 3072,
                          abuf, wbuf, 1);
            }
        }
        gsync(gen);

        // ===== P2: ew1 (scalar, 128 active blocks) -> h1 =====
        for (int idx = bid * NTHR + tid; idx < 32768; idx += NBLK * NTHR) {
            int r = idx >> 10, j = idx & 1023;
            float pr = 0.f, uv = 0.f, hx = 0.f;
            #pragma unroll
            for (int s = 0; s < 12; s++) {
                const float* P = pA + (size_t)s * 98304 + (size_t)r * 3072;
                pr += P[j]; uv += P[1024 + j]; hx += P[2048 + j];
            }
            const float* x_ = sb + (size_t)step * 65536 + (size_t)r * 2048;
            pr = sigm(pr + x_[j]);
            uv = sigm(uv + x_[1024 + j]);
            float ht = tanhf(hx * pr + sbx[(size_t)step * 32768 + r * 1024 + j]);
            float hold = h[idx];
            float m = ym[step * 32 + r];
            h1[idx] = m * (uv * hold + (1.f - uv) * ht) + (1.f - m) * hold;
        }
        // prefetch first P3 W tile
        if (bid < 280) {
            int t = bid;
            if (t < 40)       prefetchW(a.Wdec, 512, (t >> 2) * 32, (t & 3) * 128, 128, wbuf);
            else if (t < 200) { int tt = t - 40;
                                prefetchW(a.U2, 2048, (tt / 16) * 32, (tt % 16) * 128, 128, wbuf); }
            else              { int tt = t - 200;
                                prefetchW(a.Ux2, 1024, (tt >> 3) * 32, (tt & 7) * 128, 128, wbuf); }
        }
        gsync(gen);

        // ===== P3: dq + h1@U2 + h1@Ux2 partials, 280 tiles (KS=10) =====
        for (int t = bid; t < 280; t += NBLK) {
            if (t < 40) {
                int ct = t & 3, ks = t >> 2;
                GPair p = {h1, 1024, a.Wdec, 512, 1024};
                gemm_tile(&p, 1, ks, 10, ct * 128, 128,
                          pB + (size_t)ks * 16384 + ct * 128, 512, abuf, wbuf, 1);
            } else if (t < 200) {
                int tt = t - 40, ct = tt % 16, ks = tt / 16;
                GPair p = {h1, 1024, a.U2, 2048, 1024};
                gemm_tile(&p, 1, ks, 10, ct * 128, 128,
                          pA + (size_t)ks * 98304 + ct * 128, 3072, abuf, wbuf, 1);
            } else {
                int tt = t - 200, ct = tt & 7, ks = tt >> 3;
                GPair p = {h1, 1024, a.Ux2, 1024, 1024};
                gemm_tile(&p, 1, ks, 10, ct * 128, 128,
                          pA + (size_t)ks * 98304 + 2048 + ct * 128, 3072, abuf, wbuf, 1);
            }
        }
        gsync(gen);

        // ===== P4: online-softmax attention, 288 tiles (b x 9 t-chunks of 56) =====
        for (int t = bid; t < 288; t += NBLK) {
            int b = t & 31, tch = t >> 5;
            __syncthreads();
            float* dqs = SM;           // 512
            float* sc  = SM + 512;     // 56
            for (int j = tid; j < 512; j += NTHR) {
                float s = 0.f;
                #pragma unroll
                for (int sI = 0; sI < 10; sI++)
                    s += pB[(size_t)sI * 16384 + b * 512 + j];
                dqs[j] = tanhf(s);
            }
            __syncthreads();
            int t0 = tch * 56;
            int tn = 500 - t0; if (tn > 56) tn = 56;
            int w = tid >> 5, l = tid & 31;
            int hl = a.hlens[b];
            for (int tt = w; tt < tn; tt += 8) {
                const float* row = enc + ((size_t)b * 500 + t0 + tt) * 512;
                float s = 0.f;
                #pragma unroll
                for (int qq = 0; qq < 16; qq++)
                    s = fmaf(row[l + qq * 32], dqs[l + qq * 32], s);
                #pragma unroll
                for (int o = 16; o; o >>= 1) s += __shfl_xor_sync(0xffffffffu, s, o);
                if (l == 0) sc[tt] = (t0 + tt < hl) ? s : -1e9f;
            }
            __syncthreads();
            if (tid < 32) {
                float mloc = -1e30f;
                for (int i = l; i < tn; i += 32) mloc = fmaxf(mloc, sc[i]);
                #pragma unroll
                for (int o = 16; o; o >>= 1) mloc = fmaxf(mloc, __shfl_xor_sync(0xffffffffu, mloc, o));
                float ssum = 0.f;
                for (int i = l; i < tn; i += 32) {
                    float e = expf(sc[i] - mloc);
                    sc[i] = e;
                    ssum += e;
                }
                #pragma unroll
                for (int o = 16; o; o >>= 1) ssum += __shfl_xor_sync(0xffffffffu, ssum, o);
                if (l == 0) {
                    ast[(b * 9 + tch) * 2]     = mloc;
                    ast[(b * 9 + tch) * 2 + 1] = ssum;
                }
            }
            __syncthreads();
            // ctx partial: 256 threads x 4 e-cols, fp16 hs streamed evict-first
            int e0 = tid * 4;
            float4 acc = {0,0,0,0};
            const __half* hb = hsH + (size_t)b * 512000 + (size_t)t0 * 1024 + e0;
            #pragma unroll 4
            for (int tt = 0; tt < tn; tt++) {
                float wg = sc[tt];
                float2 raw = __ldcs((const float2*)(hb + (size_t)tt * 1024));
                __half2 h01 = ((__half2*)&raw)[0];
                __half2 h23 = ((__half2*)&raw)[1];
                float2 f01 = __half22float2(h01);
                float2 f23 = __half22float2(h23);
                acc.x = fmaf(wg, f01.x, acc.x);
                acc.y = fmaf(wg, f01.y, acc.y);
                acc.z = fmaf(wg, f23.x, acc.z);
                acc.w = fmaf(wg, f23.y, acc.w);
            }
            *(float4*)(cp + (size_t)(b * 9 + tch) * 1024 + e0) = acc;
            __syncthreads();
        }
        gsync(gen);

        // ===== P5: ctx combine -> cvec, 128 tiles (b x 4 e-chunks of 256) =====
        for (int t = bid; t < 128; t += NBLK) {
            int b = t & 31, ech = t >> 5;
            float M = -1e30f;
            #pragma unroll
            for (int ch = 0; ch < 9; ch++) M = fmaxf(M, ast[(b * 9 + ch) * 2]);
            float Z = 0.f;
            float scl[9];
            #pragma unroll
            for (int ch = 0; ch < 9; ch++) {
                scl[ch] = expf(ast[(b * 9 + ch) * 2] - M);
                Z += ast[(b * 9 + ch) * 2 + 1] * scl[ch];
            }
            float inv = 1.f / Z;
            int e = ech * 256 + tid;
            float s = 0.f;
            #pragma unroll
            for (int ch = 0; ch < 9; ch++)
                s = fmaf(cp[(size_t)(b * 9 + ch) * 1024 + e], scl[ch], s);
            cvec[b * 1024 + e] = s * inv;
        }
        // prefetch first P6 W tile
        if (bid < 288) {
            int t = bid;
            if (t < 144)      prefetchW(a.Wc, 2048, (t / 16) * 32, (t % 16) * 128, 128, wbuf);
            else if (t < 216) { int tt = t - 144;
                                prefetchW(a.Wcx, 1024, (tt >> 3) * 32, (tt & 7) * 128, 128, wbuf); }
            else              { int tt = t - 216;
                                prefetchW(a.We, 1024, (tt >> 3) * 32, (tt & 7) * 128, 128, wbuf); }
        }
        gsync(gen);

        // ===== P6: c@Wc | c@Wcx | c@We, 288 tiles (KS=9) =====
        for (int t = bid; t < 288; t += NBLK) {
            if (t < 144) {
                int ct = t % 16, ks = t / 16;
                GPair p = {cvec, 1024, a.Wc, 2048, 1024};
                gemm_tile(&p, 1, ks, 9, ct * 128, 128,
                          pB + (size_t)ks * 131072 + ct * 128, 4096, abuf, wbuf, 1);
            } else if (t < 216) {
                int tt = t - 144, ct = tt & 7, ks = tt >> 3;
                GPair p = {cvec, 1024, a.Wcx, 1024, 1024};
                gemm_tile(&p, 1, ks, 9, ct * 128, 128,
                          pB + (size_t)ks * 131072 + 2048 + ct * 128, 4096, abuf, wbuf, 1);
            } else {
                int tt = t - 216, ct = tt & 7, ks = tt >> 3;
                GPair p = {cvec, 1024, a.We, 1024, 1024};
                gemm_tile(&p, 1, ks, 9, ct * 128, 128,
                          pB + (size_t)ks * 131072 + 3072 + ct * 128, 4096, abuf, wbuf, 1);
            }
        }
        gsync(gen);

        // ===== P7: ew2 (scalar, 128 active blocks) -> h (=h2) =====
        for (int idx = bid * NTHR + tid; idx < 32768; idx += NBLK * NTHR) {
            int r = idx >> 10, j = idx & 1023;
            float pr = 0.f, uv = 0.f, hx = 0.f, cx = 0.f;
            #pragma unroll
            for (int s = 0; s < 10; s++) {
                const float* P = pA + (size_t)s * 98304 + (size_t)r * 3072;
                pr += P[j]; uv += P[1024 + j]; hx += P[2048 + j];
            }
            #pragma unroll
            for (int s = 0; s < 9; s++) {
                const float* P = pB + (size_t)s * 131072 + (size_t)r * 4096;
                pr += P[j]; uv += P[1024 + j]; hx += 0.f; cx += P[3072 + j];
                hx += P[2048 + j] - P[2048 + j];   // placeholder removed below
            }
            // NOTE: hx gets only pA slots (h1@Ux2); cx gets pB slot 3072 (c@Wcx);
            // pr/uv get both pA (h1@U2) and pB (c@Wc).
            // re-accumulate cleanly:
            ;
            float prv = 0.f, uvv = 0.f, hxv = 0.f, cxv = 0.f;
            #pragma unroll
            for (int s = 0; s < 10; s++) {
                const float* P = pA + (size_t)s * 98304 + (size_t)r * 3072;
                prv += P[j]; uvv += P[1024 + j]; hxv += P[2048 + j];
            }
            #pragma unroll
            for (int s = 0; s < 9; s++) {
                const float* P = pB + (size_t)s * 131072 + (size_t)r * 4096;
                prv += P[j]; uvv += P[1024 + j]; cxv += P[2048 + j] * 0.f + P[3072 + j];
                cxv += P[2048 + j] - P[2048 + j];
            }
            // Wcx partial lives at offset 2048? No: P6 wrote Wcx at 2048 and We at 3072.
            // cx (for tanh) must sum the Wcx partials (offset 2048).
            float cx2 = 0.f;
            #pragma unroll
            for (int s = 0; s < 9; s++) {
                const float* P = pB + (size_t)s * 131072 + (size_t)r * 4096;
                cx2 += P[2048 + j];
            }
            prv = sigm(prv + a.b2[j]);
            uvv = sigm(uvv + a.b2[1024 + j]);
            float ht = tanhf((hxv + a.bUx2[j]) * prv + cx2);
            float h1v = h1[idx];
            float m = ym[step * 32 + r];
            h[idx] = m * (uvv * h1v + (1.f - uvv) * ht) + (1.f - m) * h1v;
        }
        // prefetch P8 W tile (m=1 phase)
        if (bid < 256)
            prefetchW(a.Ws, 1024, (bid >> 3) * 32, (bid & 7) * 128, 128, wbuf);
        gsync(gen);

        // ===== P8: h2@Ws, 256 tiles (KS=32, m=1, W prefetched) =====
        for (int t = bid; t < 256; t += NBLK) {
            int ct = t & 7, ks = t >> 3;
            GPair p = {h, 1024, a.Ws, 1024, 1024};
            gemm_tile(&p, 1, ks, 32, ct * 128, 128,
                      pA + (size_t)ks * 32768 + ct * 128, 1024, abuf, wbuf, 1);
        }
        gsync(gen);

        // ===== P9: pool (32 Ws slots + 9 We slots + yW + bs, pairmax) -> l512 =====
        for (int idx = bid * NTHR + tid; idx < 16384; idx += NBLK * NTHR) {
            int r = idx >> 9, p2 = idx & 511;
            float2 v = *(const float2*)(a.bs + 2 * p2);
            float2 yv = *(const float2*)(yw + (size_t)step * 32768 + r * 1024 + 2 * p2);
            v.x += yv.x; v.y += yv.y;
            #pragma unroll 8
            for (int s = 0; s < 32; s++) {
                float2 pv = *(const float2*)(pA + (size_t)s * 32768 + (size_t)r * 1024 + 2 * p2);
                v.x += pv.x; v.y += pv.y;
            }
            #pragma unroll
            for (int s = 0; s < 9; s++) {
                float2 pv = *(const float2*)(pB + (size_t)s * 131072 + (size_t)r * 4096 + 3072 + 2 * p2);
                v.x += pv.x; v.y += pv.y;
            }
            l512[idx] = fmaxf(v.x, v.y);
        }
        // prefetch first P10 W tile
        if (bid < 280) {
            int ct = bid % 40, ks = bid / 40;
            int nc = 5000 - ct * 128; if (nc > 128) nc = 128;
            prefetchW(a.Wlogit, 5000, ks * 32, ct * 128, nc, wbuf);
        }
        gsync(gen);

        // ===== P10: logits5000 = l512 @ Wlogit, 280 tiles (KS=7) =====
        for (int t = bid; t < 280; t += NBLK) {
            int ct = t % 40, ks = t / 40;
            int ncols = 5000 - ct * 128; if (ncols > 128) ncols = 128;
            GPair p = {l512, 512, a.Wlogit, 5000, 512};
            gemm_tile(&p, 1, ks, 7, ct * 128, ncols,
                      pA + (size_t)ks * 160000 + ct * 128, 5000, abuf, wbuf, 1);
        }
        gsync(gen);

        // ===== P11: reduce 7 partials + local max + exp, 256 tiles =====
        for (int t = bid; t < 256; t += NBLK) {
            int b = t & 31, q = t >> 5;
            float* buf = SM;
            float* red = SM + 640;
            __syncthreads();
            float lm = -1e30f;
            for (int j0 = tid; j0 < 625; j0 += NTHR) {
                int j = q * 625 + j0;
                float v = a.blogit[j];
                #pragma unroll
                for (int s = 0; s < 7; s++)
                    v += pA[(size_t)s * 160000 + (size_t)b * 5000 + j];
                buf[j0] = v;
                lm = fmaxf(lm, v);
            }
            #pragma unroll
            for (int o = 16; o; o >>= 1) lm = fmaxf(lm, __shfl_xor_sync(0xffffffffu, lm, o));
            if ((tid & 31) == 0) red[tid >> 5] = lm;
            __syncthreads();
            float gml = red[0];
            #pragma unroll
            for (int w = 1; w < 8; w++) gml = fmaxf(gml, red[w]);
            float ls = 0.f;
            for (int j0 = tid; j0 < 625; j0 += NTHR) {
                float e = expf(buf[j0] - gml);
                expb[(size_t)b * 5000 + q * 625 + j0] = e;
                ls += e;
            }
            #pragma unroll
            for (int o = 16; o; o >>= 1) ls += __shfl_xor_sync(0xffffffffu, ls, o);
            __syncthreads();
            if ((tid & 31) == 0) red[tid >> 5] = ls;
            __syncthreads();
            if (tid == 0) {
                float tot = 0.f;
                #pragma unroll
                for (int w = 0; w < 8; w++) tot += red[w];
                ms[(b * 8 + q) * 2]     = gml;
                ms[(b * 8 + q) * 2 + 1] = tot;
            }
            __syncthreads();
        }
        // prefetch first W tile of next step's P1
        if (bid < 288) {
            int ct = bid % 24, ks = bid / 24;
            if (ct < 16) prefetchW(a.U1, 2048, ks * 32, ct * 128, 128, wbuf);
            else         prefetchW(a.Ux1, 1024, ks * 32, (ct - 16) * 128, 128, wbuf);
        }
        gsync(gen);
    }

    // ===== final 9b for step 99 =====
    for (int t = bid; t < 256; t += NBLK) {
        int b = t & 31, q = t >> 5;
        float gm = -1e30f;
        #pragma unroll
        for (int w = 0; w < 8; w++) gm = fmaxf(gm, ms[(b * 8 + w) * 2]);
        float gs = 0.f;
        #pragma unroll
        for (int w = 0; w < 8; w++)
            gs += ms[(b * 8 + w) * 2 + 1] * expf(ms[(b * 8 + w) * 2] - gm);
        float scale = expf(ms[(b * 8 + q) * 2] - gm) / gs;
        float* o = a.out + (size_t)b * 500000 + (size_t)99 * 5000 + q * 625;
        const float* src = expb + (size_t)b * 5000 + q * 625;
        for (int j0 = tid; j0 < 625; j0 += NTHR) __stcs(o + j0, src[j0] * scale);
    }

    // ===== safe barrier-counter reset =====
    __syncthreads();
    if (tid == 0) {
        unsigned r;
        asm volatile("atom.acq_rel.gpu.global.add.u32 %0, [%1], 1;"
                     : "=r"(r) : "l"(&g_bar_cnt2) : "memory");
        if (r == NBLK - 1) {
            g_bar_cnt = 0;
            g_bar_cnt2 = 0;
            __threadfence();
        }
    }
}

// ---------------- host launcher: single kernel ----------------
extern "C" void kernel_launch(void* const* d_in, const int* in_sizes, int n_in,
                              void* d_out, int out_size) {
    MKArgs a;
    a.hs     = (const float*)d_in[0];
    a.hlens  = (const int*)  d_in[1];
    a.ys     = (const int*)  d_in[2];
    a.embed  = (const float*)d_in[3];
    a.W1_W   = (const float*)d_in[4];
    a.b1_W   = (const float*)d_in[5];
    a.W1_Wx  = (const float*)d_in[6];
    a.b1_Wx  = (const float*)d_in[7];
    a.U1     = (const float*)d_in[8];
    a.Ux1    = (const float*)d_in[9];
    a.U2     = (const float*)d_in[10];
    a.b2     = (const float*)d_in[11];
    a.Wc     = (const float*)d_in[12];
    a.Ux2    = (const float*)d_in[13];
    a.bUx2   = (const float*)d_in[14];
    a.Wcx    = (const float*)d_in[15];
    a.Winit  = (const float*)d_in[16];
    a.binit  = (const float*)d_in[17];
    a.Ws     = (const float*)d_in[18];
    a.bs     = (const float*)d_in[19];
    a.Wy     = (const float*)d_in[20];
    a.We     = (const float*)d_in[21];
    a.Wlogit = (const float*)d_in[22];
    a.blogit = (const float*)d_in[23];
    a.Wenc   = (const float*)d_in[24];
    a.Wdec   = (const float*)d_in[25];
    a.out    = (float*)d_out;

    cudaFuncSetAttribute(k_mega, cudaFuncAttributeMaxDynamicSharedMemorySize, 40960);
    k_mega<<<NBLK, NTHR, 40960>>>(a);
}

// round 17
// speedup vs baseline: 1.1314x; 1.0180x over previous
#include <cuda_runtime.h>
#include <cuda_fp16.h>
#include <cstdint>
#include <math.h>

// B=32, T=500, E=1024, D=1024, EMB=256, O=5000, olen=100, A=512
#define NBLK 296
#define NTHR 256

// ---------------- scratch layout (floats) ----------------
#define OFF_EYS   ((size_t)0)          // (100,32,256)
#define OFF_SB    ((size_t)819200)     // (100,32,2048)
#define OFF_SBX   ((size_t)7372800)    // (100,32,1024)
#define OFF_ENC   ((size_t)10649600)   // (32,500,512)
#define OFF_YW    ((size_t)18841600)   // (100,32,1024) eys@Wy precomputed
#define OFF_HSUM  ((size_t)22118400)   // (32,1024)
#define OFF_H     ((size_t)22151168)
#define OFF_H1    ((size_t)22183936)
#define OFF_C     ((size_t)22216704)
#define OFF_YM    ((size_t)22249472)   // (100,32)
#define OFF_L512  ((size_t)22252672)   // (32,512)
#define OFF_MS    ((size_t)22269056)   // (32,8,2)
#define OFF_EXP   ((size_t)22269568)   // (32,5000)
#define OFF_CP    ((size_t)22429568)   // (32,9,1024) ctx partials
#define OFF_AST   ((size_t)22724480)   // (32,9,2) attn stats
#define OFF_PA    ((size_t)22725056)   // 1,179,648
#define OFF_PB    ((size_t)23904704)   // 1,179,648
#define OFF_HSH   ((size_t)25084352)   // hs fp16: 16.384M halfs = 8.192M floats
#define OFF_PC    ((size_t)33276352)   // 12*98304 = 1,179,648 (gate1 partials)
#define SZ_TOTAL  ((size_t)34456000)

__device__ float g_scratch[SZ_TOTAL];
__device__ unsigned g_bar_cnt;
__device__ unsigned g_bar_cnt2;

// ---------------- grid barrier: REDG arrive + acquire poll ----------------
__device__ __forceinline__ void gsync(unsigned& gen) {
    gen += NBLK;
    __syncthreads();
    if (threadIdx.x == 0) {
        asm volatile("red.release.gpu.global.add.u32 [%0], 1;"
                     :: "l"(&g_bar_cnt) : "memory");
        unsigned v;
        while (true) {
            asm volatile("ld.acquire.gpu.global.u32 %0, [%1];"
                         : "=r"(v) : "l"(&g_bar_cnt) : "memory");
            if ((int)(v - gen) >= 0) break;
        }
    }
    __syncthreads();
}

__device__ __forceinline__ float sigm(float x) { return 1.f / (1.f + expf(-x)); }

__device__ __forceinline__ unsigned long long mkpol() {
    unsigned long long p;
    asm("createpolicy.fractional.L2::evict_last.b64 %0, 1.0;" : "=l"(p));
    return p;
}
__device__ __forceinline__ float ldg_el(const float* p, unsigned long long pol) {
    float v;
    asm volatile("ld.global.nc.L2::cache_hint.f32 %0, [%1], %2;"
                 : "=f"(v) : "l"(p), "l"(pol));
    return v;
}

// ---------------- GEMM building blocks (32 rows x 128 cols tile) ----------------
__device__ __forceinline__ void load_A(const float* A, int ldA, int k0, float* sAT) {
    int tid = threadIdx.x;
    int r = tid & 31, q = tid >> 5;
    float4 v = *(const float4*)(A + (size_t)r * ldA + k0 + q * 4);
    sAT[(q*4+0)*32 + r] = v.x; sAT[(q*4+1)*32 + r] = v.y;
    sAT[(q*4+2)*32 + r] = v.z; sAT[(q*4+3)*32 + r] = v.w;
}

// cp.async with L2 evict_last: weights stay L2-resident across the step loop
__device__ __forceinline__ void load_W_async(const float* W, int ldW, int k0,
                                             int colBase, int ncols, float* sWdst) {
    unsigned sbase = (unsigned)__cvta_generic_to_shared(sWdst);
    int tid = threadIdx.x;
    #pragma unroll
    for (int v4 = 0; v4 < 4; v4++) {
        int id = tid + v4 * 256;
        int kr = id >> 5;
        int c4 = (id & 31) << 2;
        int rem = ncols - c4;
        int sz = rem >= 4 ? 16 : (rem > 0 ? rem * 4 : 0);
        int cc = (sz > 0) ? c4 : 0;
        const float* src = W + (size_t)(k0 + kr) * ldW + colBase + cc;
        unsigned d = sbase + (unsigned)((kr * 128 + c4) * 4);
        asm volatile(
            "{\n\t"
            ".reg .b64 pol;\n\t"
            "createpolicy.fractional.L2::evict_last.b64 pol, 1.0;\n\t"
            "cp.async.cg.shared.global.L2::cache_hint [%0], [%1], 16, %2, pol;\n\t"
            "}"
            :: "r"(d), "l"(src), "r"(sz));
    }
}

__device__ __forceinline__ void prefetchW(const float* W, int ldW, int k0,
                                          int colBase, int ncols, float* wbuf) {
    __syncthreads();   // ensure prior phase readers of wbuf are done
    load_W_async(W, ldW, k0, colBase, ncols, wbuf);
    asm volatile("cp.async.commit_group;" ::: "memory");
}

// packed f32x2 MMA, 8 rows x 2 cols per thread
__device__ __forceinline__ void mma_chunk(unsigned long long acc[4][2],
                                          const float* sAT, const float* sW) {
    int tid = threadIdx.x;
    int ct = tid & 63, rt = tid >> 6;
    #pragma unroll
    for (int kk = 0; kk < 32; kk++) {
        const unsigned long long* ap =
            (const unsigned long long*)(sAT + kk * 32 + rt * 8);
        unsigned long long a0 = ap[0], a1 = ap[1], a2 = ap[2], a3 = ap[3];
        float2 w = *(const float2*)(sW + kk * 128 + ct * 2);
        unsigned long long w0, w1;
        asm("mov.b64 %0, {%1,%1};" : "=l"(w0) : "f"(w.x));
        asm("mov.b64 %0, {%1,%1};" : "=l"(w1) : "f"(w.y));
        #define F2X(ac, av, wv) \
            asm("fma.rn.f32x2 %0, %1, %2, %0;" : "+l"(ac) : "l"(av), "l"(wv));
        F2X(acc[0][0], a0, w0) F2X(acc[0][1], a0, w1)
        F2X(acc[1][0], a1, w0) F2X(acc[1][1], a1, w1)
        F2X(acc[2][0], a2, w0) F2X(acc[2][1], a2, w1)
        F2X(acc[3][0], a3, w0) F2X(acc[3][1], a3, w1)
        #undef F2X
    }
}

__device__ __forceinline__ void store_tile(unsigned long long acc[4][2],
                                           float* outBase, int Ntot, int ncols) {
    int tid = threadIdx.x;
    int ct = tid & 63, rt = tid >> 6;
    int c = ct * 2;
    if (c + 2 > ncols) return;
    #pragma unroll
    for (int i = 0; i < 4; i++) {
        float lo0, hi0, lo1, hi1;
        asm("mov.b64 {%0,%1}, %2;" : "=f"(lo0), "=f"(hi0) : "l"(acc[i][0]));
        asm("mov.b64 {%0,%1}, %2;" : "=f"(lo1), "=f"(hi1) : "l"(acc[i][1]));
        float* d0 = outBase + (size_t)(rt * 8 + 2 * i) * Ntot + c;
        float* d1 = outBase + (size_t)(rt * 8 + 2 * i + 1) * Ntot + c;
        *(float2*)d0 = make_float2(lo0, lo1);
        *(float2*)d1 = make_float2(hi0, hi1);
    }
}

struct GPair { const float* A; int ldA; const float* W; int ldW; int K; };

__device__ void gemm_tile(const GPair* pr, int np, int ks, int KS,
                          int colBase, int ncols, float* outSlot, int Ntot,
                          float* abuf, float* wbuf, int wpre) {
    unsigned long long acc[4][2] = {};
    int pidx[8], koff[8];
    int m = 0, gc = 0;
    for (int p = 0; p < np; p++)
        for (int k0 = 0; k0 < pr[p].K; k0 += 32)
            if ((gc++ % KS) == ks) { pidx[m] = p; koff[m] = k0; m++; }

    __syncthreads();
    if (m > 0) {
        if (!wpre) {
            load_W_async(pr[pidx[0]].W, pr[pidx[0]].ldW, koff[0], colBase, ncols, wbuf);
            asm volatile("cp.async.commit_group;" ::: "memory");
        }
        load_A(pr[pidx[0]].A, pr[pidx[0]].ldA, koff[0], abuf);
    }
    for (int i = 0; i < m; i++) {
        asm volatile("cp.async.wait_group 0;" ::: "memory");
        __syncthreads();
        if (i + 1 < m) {
            load_W_async(pr[pidx[i+1]].W, pr[pidx[i+1]].ldW, koff[i+1],
                         colBase, ncols, wbuf + ((i + 1) & 1) * 4096);
            asm volatile("cp.async.commit_group;" ::: "memory");
            load_A(pr[pidx[i+1]].A, pr[pidx[i+1]].ldA, koff[i+1],
                   abuf + ((i + 1) & 1) * 1024);
        }
        mma_chunk(acc, abuf + (i & 1) * 1024, wbuf + (i & 1) * 4096);
    }
    store_tile(acc, outSlot, Ntot, ncols);
}

// ---------------- 64x64 tiled SGEMM (precompute) ----------
__device__ void tiled64(const float* __restrict__ A, const float* __restrict__ W,
                        const float* __restrict__ bias, float* __restrict__ C,
                        int N, int K, int act, int cx, int cy, float* USM) {
    float* sAT = USM;          // [16][68]
    float* sW  = USM + 1088;   // [16][64]
    int rowBase = cy << 6;
    int colBase = cx << 6;
    int tx = threadIdx.x & 15;
    int ty = threadIdx.x >> 4;
    float acc[4][4];
    #pragma unroll
    for (int i = 0; i < 4; i++)
        #pragma unroll
        for (int j = 0; j < 4; j++) acc[i][j] = 0.f;

    for (int k0 = 0; k0 < K; k0 += 16) {
        __syncthreads();
        {
            int r = threadIdx.x >> 2;
            int c4 = (threadIdx.x & 3) << 2;
            float4 v = *(const float4*)(A + (size_t)(rowBase + r) * K + k0 + c4);
            sAT[(c4+0)*68 + r] = v.x; sAT[(c4+1)*68 + r] = v.y;
            sAT[(c4+2)*68 + r] = v.z; sAT[(c4+3)*68 + r] = v.w;
            int kr = threadIdx.x >> 4;
            int wc = (threadIdx.x & 15) << 2;
            *(float4*)&sW[kr*64 + wc] = *(const float4*)(W + (size_t)(k0 + kr) * N + colBase + wc);
        }
        __syncthreads();
        #pragma unroll
        for (int kk = 0; kk < 16; kk++) {
            float4 a4 = *(const float4*)&sAT[kk*68 + (ty << 2)];
            float4 w4 = *(const float4*)&sW[kk*64 + (tx << 2)];
            float av[4] = {a4.x, a4.y, a4.z, a4.w};
            float wv[4] = {w4.x, w4.y, w4.z, w4.w};
            #pragma unroll
            for (int i = 0; i < 4; i++)
                #pragma unroll
                for (int j = 0; j < 4; j++)
                    acc[i][j] = fmaf(av[i], wv[j], acc[i][j]);
        }
    }
    #pragma unroll
    for (int i = 0; i < 4; i++) {
        int r = rowBase + (ty << 2) + i;
        #pragma unroll
        for (int j = 0; j < 4; j++) {
            int c = colBase + (tx << 2) + j;
            float v = acc[i][j];
            if (bias) v += bias[c];
            if (act == 1) v = tanhf(v);
            C[(size_t)r * N + c] = v;
        }
    }
}

// ---------------- megakernel ----------------
struct MKArgs {
    const float *hs, *embed, *W1_W, *b1_W, *W1_Wx, *b1_Wx, *Wenc;
    const float *U1, *Ux1, *U2, *b2, *Wc, *Ux2, *bUx2, *Wcx;
    const float *Ws, *bs, *Wy, *We, *Wlogit, *blogit, *Wdec, *Winit, *binit;
    const int *hlens, *ys;
    float* out;
};

__global__ void __launch_bounds__(NTHR, 2) k_mega(MKArgs a) {
    extern __shared__ float SM[];
    float* abuf = SM;          // 2048 floats
    float* wbuf = SM + 2048;   // 8192 floats

    float* eys  = g_scratch + OFF_EYS;
    float* sb   = g_scratch + OFF_SB;
    float* sbx  = g_scratch + OFF_SBX;
    float* enc  = g_scratch + OFF_ENC;
    float* yw   = g_scratch + OFF_YW;
    float* hsum = g_scratch + OFF_HSUM;
    float* h    = g_scratch + OFF_H;
    float* h1   = g_scratch + OFF_H1;
    float* cvec = g_scratch + OFF_C;
    float* ym   = g_scratch + OFF_YM;
    float* l512 = g_scratch + OFF_L512;
    float* ms   = g_scratch + OFF_MS;
    float* expb = g_scratch + OFF_EXP;
    float* cp   = g_scratch + OFF_CP;
    float* ast  = g_scratch + OFF_AST;
    float* pA   = g_scratch + OFF_PA;
    float* pB   = g_scratch + OFF_PB;
    float* pC   = g_scratch + OFF_PC;
    __half* hsH = (__half*)(g_scratch + OFF_HSH);

    const int tid = threadIdx.x;
    const int bid = blockIdx.x;
    unsigned gen = 0;
    unsigned long long pol = mkpol();

    // ===== phase 0a: setup (ymask, eys gather, hs->fp16, hsum) =====
    if (bid == 0 && tid < 32) {
        int b = tid;
        int yl = 0;
        for (int j = 0; j < 99; j++) yl += (a.ys[b * 99 + j] != -1) ? 1 : 0;
        for (int i = 0; i < 100; i++)
            ym[i * 32 + b] = (i < yl + 1) ? 1.f : 0.f;
    }
    for (int idx4 = bid * NTHR + tid; idx4 < 204800; idx4 += NBLK * NTHR) {
        int row = idx4 >> 6;
        int i = row >> 5, b = row & 31;
        int tok = 4999;
        if (i > 0) { int v = a.ys[b * 99 + i - 1]; tok = (v < 0) ? 4999 : v; }
        int c4 = (idx4 & 63) << 2;
        *(float4*)&eys[(size_t)row * 256 + c4] =
            *(const float4*)&a.embed[(size_t)tok * 256 + c4];
    }
    for (int i4 = bid * NTHR + tid; i4 < 4096000; i4 += NBLK * NTHR) {
        float4 v = *((const float4*)a.hs + i4);
        __half2 p0 = __floats2half2_rn(v.x, v.y);
        __half2 p1 = __floats2half2_rn(v.z, v.w);
        ((__half2*)hsH)[(size_t)i4 * 2]     = p0;
        ((__half2*)hsH)[(size_t)i4 * 2 + 1] = p1;
    }
    for (int t = bid; t < 256; t += NBLK) {
        int b = t >> 3, ech = t & 7;
        if (tid < 128) {
            int e = ech * 128 + tid;
            const float* base = a.hs + (size_t)b * 512000 + e;
            float s0 = 0.f, s1 = 0.f;
            for (int tt = 0; tt < 500; tt += 2) {
                s0 += base[(size_t)tt * 1024];
                s1 += base[(size_t)(tt + 1) * 1024];
            }
            hsum[b * 1024 + e] = (s0 + s1) / (float)a.hlens[b];
        }
    }
    gsync(gen);

    // ===== phase 0b: sb, sbx, yW, enc via 64x64 tiles (5200 tiles) =====
    for (int t = bid; t < 5200; t += NBLK) {
        if (t < 1600)       tiled64(eys, a.W1_W, a.b1_W, sb, 2048, 256, 0,
                                    t % 32, t / 32, SM);
        else if (t < 2400)  tiled64(eys, a.W1_Wx, a.b1_Wx, sbx, 1024, 256, 0,
                                    (t - 1600) % 16, (t - 1600) / 16, SM);
        else if (t < 3200)  tiled64(eys, a.Wy, nullptr, yw, 1024, 256, 0,
                                    (t - 2400) % 16, (t - 2400) / 16, SM);
        else                tiled64(a.hs, a.Wenc, nullptr, enc, 512, 1024, 1,
                                    (t - 3200) % 8, (t - 3200) / 8, SM);
    }
    gsync(gen);

    // ===== h0 = hsum @ Winit + binit : 128 tiles =====
    for (int t = bid; t < 128; t += NBLK) {
        int ct = t & 7, ks = t >> 3;
        GPair p = {hsum, 1024, a.Winit, 1024, 1024};
        gemm_tile(&p, 1, ks, 16, ct * 128, 128,
                  pA + (size_t)ks * 32768 + ct * 128, 1024, abuf, wbuf, 0);
    }
    gsync(gen);
    for (int idx = bid * NTHR + tid; idx < 32768; idx += NBLK * NTHR) {
        float s = a.binit[idx & 1023];
        #pragma unroll 4
        for (int sI = 0; sI < 16; sI++) s += pA[(size_t)sI * 32768 + idx];
        h[idx] = s;
    }
    if (bid < 288) {
        int ct = bid % 24, ks = bid / 24;
        if (ct < 16) prefetchW(a.U1, 2048, ks * 32, ct * 128, 128, wbuf);
        else         prefetchW(a.Ux1, 1024, ks * 32, (ct - 16) * 128, 128, wbuf);
    }
    gsync(gen);

    for (int step = 0; step < 100; step++) {
        // ===== PA: [step>0: P11 reduce of prev logits] + gate1 GEMM -> pC =====
        if (step > 0 && bid < 256) {
            int b = bid & 31, q = bid >> 5;
            float* buf = SM;               // 625 (abuf region; gemm resets later)
            float* red = SM + 640;
            __syncthreads();
            float lm = -1e30f;
            for (int j0 = tid; j0 < 625; j0 += NTHR) {
                int j = q * 625 + j0;
                float v = a.blogit[j];
                #pragma unroll
                for (int s = 0; s < 7; s++)
                    v += pA[(size_t)s * 160000 + (size_t)b * 5000 + j];
                buf[j0] = v;
                lm = fmaxf(lm, v);
            }
            #pragma unroll
            for (int o = 16; o; o >>= 1) lm = fmaxf(lm, __shfl_xor_sync(0xffffffffu, lm, o));
            if ((tid & 31) == 0) red[tid >> 5] = lm;
            __syncthreads();
            float gml = red[0];
            #pragma unroll
            for (int w = 1; w < 8; w++) gml = fmaxf(gml, red[w]);
            float ls = 0.f;
            for (int j0 = tid; j0 < 625; j0 += NTHR) {
                float e = expf(buf[j0] - gml);
                expb[(size_t)b * 5000 + q * 625 + j0] = e;
                ls += e;
            }
            #pragma unroll
            for (int o = 16; o; o >>= 1) ls += __shfl_xor_sync(0xffffffffu, ls, o);
            __syncthreads();
            if ((tid & 31) == 0) red[tid >> 5] = ls;
            __syncthreads();
            if (tid == 0) {
                float tot = 0.f;
                #pragma unroll
                for (int w = 0; w < 8; w++) tot += red[w];
                ms[(b * 8 + q) * 2]     = gml;
                ms[(b * 8 + q) * 2 + 1] = tot;
            }
            __syncthreads();
        }
        if (bid < 288) {
            int ct = bid % 24, ks = bid / 24;      // KS=12
            if (ct < 16) {
                GPair p = {h, 1024, a.U1, 2048, 1024};
                gemm_tile(&p, 1, ks, 12, ct * 128, 128,
                          pC + (size_t)ks * 98304 + ct * 128, 3072, abuf, wbuf, 1);
            } else {
                GPair p = {h, 1024, a.Ux1, 1024, 1024};
                gemm_tile(&p, 1, ks, 12, (ct - 16) * 128, 128,
                          pC + (size_t)ks * 98304 + 2048 + (ct - 16) * 128, 3072,
                          abuf, wbuf, 1);
            }
        }
        gsync(gen);

        // ===== PB: [step>0: 9b output write] + ew1 -> h1 =====
        if (step > 0) {
            for (int t = bid; t < 256; t += NBLK) {
                int b = t & 31, q = t >> 5;
                float gm = -1e30f;
                #pragma unroll
                for (int w = 0; w < 8; w++) gm = fmaxf(gm, ms[(b * 8 + w) * 2]);
                float gs = 0.f;
                #pragma unroll
                for (int w = 0; w < 8; w++)
                    gs += ms[(b * 8 + w) * 2 + 1] * expf(ms[(b * 8 + w) * 2] - gm);
                float scale = expf(ms[(b * 8 + q) * 2] - gm) / gs;
                float* o = a.out + (size_t)b * 500000 + (size_t)(step - 1) * 5000 + q * 625;
                const float* src = expb + (size_t)b * 5000 + q * 625;
                for (int j0 = tid; j0 < 625; j0 += NTHR) __stcs(o + j0, src[j0] * scale);
            }
        }
        for (int idx = bid * NTHR + tid; idx < 32768; idx += NBLK * NTHR) {
            int r = idx >> 10, j = idx & 1023;
            float pr = 0.f, uv = 0.f, hx = 0.f;
            #pragma unroll
            for (int s = 0; s < 12; s++) {
                const float* P = pC + (size_t)s * 98304 + (size_t)r * 3072;
                pr += P[j]; uv += P[1024 + j]; hx += P[2048 + j];
            }
            const float* x_ = sb + (size_t)step * 65536 + (size_t)r * 2048;
            pr = sigm(pr + x_[j]);
            uv = sigm(uv + x_[1024 + j]);
            float ht = tanhf(hx * pr + sbx[(size_t)step * 32768 + r * 1024 + j]);
            float hold = h[idx];
            float m = ym[step * 32 + r];
            h1[idx] = m * (uv * hold + (1.f - uv) * ht) + (1.f - m) * hold;
        }
        if (bid < 280) {
            int t = bid;
            if (t < 40)       prefetchW(a.Wdec, 512, (t >> 2) * 32, (t & 3) * 128, 128, wbuf);
            else if (t < 200) { int tt = t - 40;
                                prefetchW(a.U2, 2048, (tt / 16) * 32, (tt % 16) * 128, 128, wbuf); }
            else              { int tt = t - 200;
                                prefetchW(a.Ux2, 1024, (tt >> 3) * 32, (tt & 7) * 128, 128, wbuf); }
        }
        gsync(gen);

        // ===== P3: dq + h1@U2 + h1@Ux2 partials, 280 tiles (KS=10) =====
        for (int t = bid; t < 280; t += NBLK) {
            if (t < 40) {
                int ct = t & 3, ks = t >> 2;
                GPair p = {h1, 1024, a.Wdec, 512, 1024};
                gemm_tile(&p, 1, ks, 10, ct * 128, 128,
                          pB + (size_t)ks * 16384 + ct * 128, 512, abuf, wbuf, 1);
            } else if (t < 200) {
                int tt = t - 40, ct = tt % 16, ks = tt / 16;
                GPair p = {h1, 1024, a.U2, 2048, 1024};
                gemm_tile(&p, 1, ks, 10, ct * 128, 128,
                          pA + (size_t)ks * 98304 + ct * 128, 3072, abuf, wbuf, 1);
            } else {
                int tt = t - 200, ct = tt & 7, ks = tt >> 3;
                GPair p = {h1, 1024, a.Ux2, 1024, 1024};
                gemm_tile(&p, 1, ks, 10, ct * 128, 128,
                          pA + (size_t)ks * 98304 + 2048 + ct * 128, 3072, abuf, wbuf, 1);
            }
        }
        gsync(gen);

        // ===== P4: online-softmax attention, 288 tiles (b x 9 t-chunks of 56) =====
        for (int t = bid; t < 288; t += NBLK) {
            int b = t & 31, tch = t >> 5;
            __syncthreads();
            float* dqs = SM;           // 512
            float* sc  = SM + 512;     // 56
            for (int j = tid; j < 512; j += NTHR) {
                float s = 0.f;
                #pragma unroll
                for (int sI = 0; sI < 10; sI++)
                    s += pB[(size_t)sI * 16384 + b * 512 + j];
                dqs[j] = tanhf(s);
            }
            __syncthreads();
            int t0 = tch * 56;
            int tn = 500 - t0; if (tn > 56) tn = 56;
            int w = tid >> 5, l = tid & 31;
            int hl = a.hlens[b];
            for (int tt = w; tt < tn; tt += 8) {
                const float* row = enc + ((size_t)b * 500 + t0 + tt) * 512;
                float s = 0.f;
                #pragma unroll
                for (int qq = 0; qq < 16; qq++)
                    s = fmaf(ldg_el(row + l + qq * 32, pol), dqs[l + qq * 32], s);
                #pragma unroll
                for (int o = 16; o; o >>= 1) s += __shfl_xor_sync(0xffffffffu, s, o);
                if (l == 0) sc[tt] = (t0 + tt < hl) ? s : -1e9f;
            }
            __syncthreads();
            if (tid < 32) {
                float mloc = -1e30f;
                for (int i = l; i < tn; i += 32) mloc = fmaxf(mloc, sc[i]);
                #pragma unroll
                for (int o = 16; o; o >>= 1) mloc = fmaxf(mloc, __shfl_xor_sync(0xffffffffu, mloc, o));
                float ssum = 0.f;
                for (int i = l; i < tn; i += 32) {
                    float e = expf(sc[i] - mloc);
                    sc[i] = e;
                    ssum += e;
                }
                #pragma unroll
                for (int o = 16; o; o >>= 1) ssum += __shfl_xor_sync(0xffffffffu, ssum, o);
                if (l == 0) {
                    ast[(b * 9 + tch) * 2]     = mloc;
                    ast[(b * 9 + tch) * 2 + 1] = ssum;
                }
            }
            __syncthreads();
            int e0 = tid * 4;
            float4 acc = {0,0,0,0};
            const __half* hb = hsH + (size_t)b * 512000 + (size_t)t0 * 1024 + e0;
            #pragma unroll 4
            for (int tt = 0; tt < tn; tt++) {
                float wg = sc[tt];
                float2 raw = __ldcs((const float2*)(hb + (size_t)tt * 1024));
                __half2 h01 = ((__half2*)&raw)[0];
                __half2 h23 = ((__half2*)&raw)[1];
                float2 f01 = __half22float2(h01);
                float2 f23 = __half22float2(h23);
                acc.x = fmaf(wg, f01.x, acc.x);
                acc.y = fmaf(wg, f01.y, acc.y);
                acc.z = fmaf(wg, f23.x, acc.z);
                acc.w = fmaf(wg, f23.y, acc.w);
            }
            *(float4*)(cp + (size_t)(b * 9 + tch) * 1024 + e0) = acc;
            __syncthreads();
        }
        gsync(gen);

        // ===== P5: ctx combine -> cvec, 128 tiles =====
        for (int t = bid; t < 128; t += NBLK) {
            int b = t & 31, ech = t >> 5;
            float M = -1e30f;
            #pragma unroll
            for (int ch = 0; ch < 9; ch++) M = fmaxf(M, ast[(b * 9 + ch) * 2]);
            float Z = 0.f;
            float scl[9];
            #pragma unroll
            for (int ch = 0; ch < 9; ch++) {
                scl[ch] = expf(ast[(b * 9 + ch) * 2] - M);
                Z += ast[(b * 9 + ch) * 2 + 1] * scl[ch];
            }
            float inv = 1.f / Z;
            int e = ech * 256 + tid;
            float s = 0.f;
            #pragma unroll
            for (int ch = 0; ch < 9; ch++)
                s = fmaf(cp[(size_t)(b * 9 + ch) * 1024 + e], scl[ch], s);
            cvec[b * 1024 + e] = s * inv;
        }
        if (bid < 288) {
            int t = bid;
            if (t < 144)      prefetchW(a.Wc, 2048, (t / 16) * 32, (t % 16) * 128, 128, wbuf);
            else if (t < 216) { int tt = t - 144;
                                prefetchW(a.Wcx, 1024, (tt >> 3) * 32, (tt & 7) * 128, 128, wbuf); }
            else              { int tt = t - 216;
                                prefetchW(a.We, 1024, (tt >> 3) * 32, (tt & 7) * 128, 128, wbuf); }
        }
        gsync(gen);

        // ===== P6: c@Wc | c@Wcx | c@We, 288 tiles (KS=9) =====
        for (int t = bid; t < 288; t += NBLK) {
            if (t < 144) {
                int ct = t % 16, ks = t / 16;
                GPair p = {cvec, 1024, a.Wc, 2048, 1024};
                gemm_tile(&p, 1, ks, 9, ct * 128, 128,
                          pB + (size_t)ks * 131072 + ct * 128, 4096, abuf, wbuf, 1);
            } else if (t < 216) {
                int tt = t - 144, ct = tt & 7, ks = tt >> 3;
                GPair p = {cvec, 1024, a.Wcx, 1024, 1024};
                gemm_tile(&p, 1, ks, 9, ct * 128, 128,
                          pB + (size_t)ks * 131072 + 2048 + ct * 128, 4096, abuf, wbuf, 1);
            } else {
                int tt = t - 216, ct = tt & 7, ks = tt >> 3;
                GPair p = {cvec, 1024, a.We, 1024, 1024};
                gemm_tile(&p, 1, ks, 9, ct * 128, 128,
                          pB + (size_t)ks * 131072 + 3072 + ct * 128, 4096, abuf, wbuf, 1);
            }
        }
        gsync(gen);

        // ===== P7: ew2 (clean single pass) -> h (=h2) =====
        for (int idx = bid * NTHR + tid; idx < 32768; idx += NBLK * NTHR) {
            int r = idx >> 10, j = idx & 1023;
            float prv = 0.f, uvv = 0.f, hxv = 0.f, cxv = 0.f;
            #pragma unroll
            for (int s = 0; s < 10; s++) {
                const float* P = pA + (size_t)s * 98304 + (size_t)r * 3072;
                prv += P[j]; uvv += P[1024 + j]; hxv += P[2048 + j];
            }
            #pragma unroll
            for (int s = 0; s < 9; s++) {
                const float* P = pB + (size_t)s * 131072 + (size_t)r * 4096;
                prv += P[j]; uvv += P[1024 + j]; cxv += P[2048 + j];
            }
            prv = sigm(prv + a.b2[j]);
            uvv = sigm(uvv + a.b2[1024 + j]);
            float ht = tanhf((hxv + a.bUx2[j]) * prv + cxv);
            float h1v = h1[idx];
            float m = ym[step * 32 + r];
            h[idx] = m * (uvv * h1v + (1.f - uvv) * ht) + (1.f - m) * h1v;
        }
        if (bid < 256)
            prefetchW(a.Ws, 1024, (bid >> 3) * 32, (bid & 7) * 128, 128, wbuf);
        gsync(gen);

        // ===== P8: h2@Ws, 256 tiles (KS=32, m=1, W prefetched) =====
        for (int t = bid; t < 256; t += NBLK) {
            int ct = t & 7, ks = t >> 3;
            GPair p = {h, 1024, a.Ws, 1024, 1024};
            gemm_tile(&p, 1, ks, 32, ct * 128, 128,
                      pA + (size_t)ks * 32768 + ct * 128, 1024, abuf, wbuf, 1);
        }
        gsync(gen);

        // ===== P9: pool -> l512 =====
        for (int idx = bid * NTHR + tid; idx < 16384; idx += NBLK * NTHR) {
            int r = idx >> 9, p2 = idx & 511;
            float2 v = *(const float2*)(a.bs + 2 * p2);
            float2 yv = *(const float2*)(yw + (size_t)step * 32768 + r * 1024 + 2 * p2);
            v.x += yv.x; v.y += yv.y;
            #pragma unroll 8
            for (int s = 0; s < 32; s++) {
                float2 pv = *(const float2*)(pA + (size_t)s * 32768 + (size_t)r * 1024 + 2 * p2);
                v.x += pv.x; v.y += pv.y;
            }
            #pragma unroll
            for (int s = 0; s < 9; s++) {
                float2 pv = *(const float2*)(pB + (size_t)s * 131072 + (size_t)r * 4096 + 3072 + 2 * p2);
                v.x += pv.x; v.y += pv.y;
            }
            l512[idx] = fmaxf(v.x, v.y);
        }
        if (bid < 280) {
            int ct = bid % 40, ks = bid / 40;
            int nc = 5000 - ct * 128; if (nc > 128) nc = 128;
            prefetchW(a.Wlogit, 5000, ks * 32, ct * 128, nc, wbuf);
        }
        gsync(gen);

        // ===== P10: logits5000 = l512 @ Wlogit, 280 tiles (KS=7) =====
        for (int t = bid; t < 280; t += NBLK) {
            int ct = t % 40, ks = t / 40;
            int ncols = 5000 - ct * 128; if (ncols > 128) ncols = 128;
            GPair p = {l512, 512, a.Wlogit, 5000, 512};
            gemm_tile(&p, 1, ks, 7, ct * 128, ncols,
                      pA + (size_t)ks * 160000 + ct * 128, 5000, abuf, wbuf, 1);
        }
        // prefetch first W tile of next phase-A gate1 GEMM
        if (bid < 288) {
            int ct = bid % 24, ks = bid / 24;
            if (ct < 16) prefetchW(a.U1, 2048, ks * 32, ct * 128, 128, wbuf);
            else         prefetchW(a.Ux1, 1024, ks * 32, (ct - 16) * 128, 128, wbuf);
        }
        gsync(gen);
    }

    // ===== final P11 for step 99 =====
    for (int t = bid; t < 256; t += NBLK) {
        int b = t & 31, q = t >> 5;
        float* buf = SM;
        float* red = SM + 640;
        __syncthreads();
        float lm = -1e30f;
        for (int j0 = tid; j0 < 625; j0 += NTHR) {
            int j = q * 625 + j0;
            float v = a.blogit[j];
            #pragma unroll
            for (int s = 0; s < 7; s++)
                v += pA[(size_t)s * 160000 + (size_t)b * 5000 + j];
            buf[j0] = v;
            lm = fmaxf(lm, v);
        }
        #pragma unroll
        for (int o = 16; o; o >>= 1) lm = fmaxf(lm, __shfl_xor_sync(0xffffffffu, lm, o));
        if ((tid & 31) == 0) red[tid >> 5] = lm;
        __syncthreads();
        float gml = red[0];
        #pragma unroll
        for (int w = 1; w < 8; w++) gml = fmaxf(gml, red[w]);
        float ls = 0.f;
        for (int j0 = tid; j0 < 625; j0 += NTHR) {
            float e = expf(buf[j0] - gml);
            expb[(size_t)b * 5000 + q * 625 + j0] = e;
            ls += e;
        }
        #pragma unroll
        for (int o = 16; o; o >>= 1) ls += __shfl_xor_sync(0xffffffffu, ls, o);
        __syncthreads();
        if ((tid & 31) == 0) red[tid >> 5] = ls;
        __syncthreads();
        if (tid == 0) {
            float tot = 0.f;
            #pragma unroll
            for (int w = 0; w < 8; w++) tot += red[w];
            ms[(b * 8 + q) * 2]     = gml;
            ms[(b * 8 + q) * 2 + 1] = tot;
        }
        __syncthreads();
    }
    gsync(gen);

    // ===== final 9b for step 99 =====
    for (int t = bid; t < 256; t += NBLK) {
        int b = t & 31, q = t >> 5;
        float gm = -1e30f;
        #pragma unroll
        for (int w = 0; w < 8; w++) gm = fmaxf(gm, ms[(b * 8 + w) * 2]);
        float gs = 0.f;
        #pragma unroll
        for (int w = 0; w < 8; w++)
            gs += ms[(b * 8 + w) * 2 + 1] * expf(ms[(b * 8 + w) * 2] - gm);
        float scale = expf(ms[(b * 8 + q) * 2] - gm) / gs;
        float* o = a.out + (size_t)b * 500000 + (size_t)99 * 5000 + q * 625;
        const float* src = expb + (size_t)b * 5000 + q * 625;
        for (int j0 = tid; j0 < 625; j0 += NTHR) __stcs(o + j0, src[j0] * scale);
    }

    // ===== safe barrier-counter reset =====
    __syncthreads();
    if (tid == 0) {
        unsigned r;
        asm volatile("atom.acq_rel.gpu.global.add.u32 %0, [%1], 1;"
                     : "=r"(r) : "l"(&g_bar_cnt2) : "memory");
        if (r == NBLK - 1) {
            g_bar_cnt = 0;
            g_bar_cnt2 = 0;
            __threadfence();
        }
    }
}

// ---------------- host launcher: single kernel ----------------
extern "C" void kernel_launch(void* const* d_in, const int* in_sizes, int n_in,
                              void* d_out, int out_size) {
    MKArgs a;
    a.hs     = (const float*)d_in[0];
    a.hlens  = (const int*)  d_in[1];
    a.ys     = (const int*)  d_in[2];
    a.embed  = (const float*)d_in[3];
    a.W1_W   = (const float*)d_in[4];
    a.b1_W   = (const float*)d_in[5];
    a.W1_Wx  = (const float*)d_in[6];
    a.b1_Wx  = (const float*)d_in[7];
    a.U1     = (const float*)d_in[8];
    a.Ux1    = (const float*)d_in[9];
    a.U2     = (const float*)d_in[10];
    a.b2     = (const float*)d_in[11];
    a.Wc     = (const float*)d_in[12];
    a.Ux2    = (const float*)d_in[13];
    a.bUx2   = (const float*)d_in[14];
    a.Wcx    = (const float*)d_in[15];
    a.Winit  = (const float*)d_in[16];
    a.binit  = (const float*)d_in[17];
    a.Ws     = (const float*)d_in[18];
    a.bs     = (const float*)d_in[19];
    a.Wy     = (const float*)d_in[20];
    a.We     = (const float*)d_in[21];
    a.Wlogit = (const float*)d_in[22];
    a.blogit = (const float*)d_in[23];
    a.Wenc   = (const float*)d_in[24];
    a.Wdec   = (const float*)d_in[25];
    a.out    = (float*)d_out;

    cudaFuncSetAttribute(k_mega, cudaFuncAttributeMaxDynamicSharedMemorySize, 40960);
    k_mega<<<NBLK, NTHR, 40960>>>(a);
}